// round 11
// baseline (speedup 1.0000x reference)
#include <cuda_runtime.h>
#include <cuda_bf16.h>
#include <math.h>
#include <stdint.h>

#define BB 8
#define NN 1024
#define SS 1024
#define CC 768
#define HH 12
#define DD 64
#define SCALEF 0.125f

#define LDT 72        // bf16 elems per 64-wide tile row (144B, conflict-free)
#define LDP2 72       // P tile row stride (64-wide chunk P)
#define NT 512
#define TILEB (128 * LDT * 2)   // 18432 B per 128x64 bf16 tile
#define KTILEB (64 * LDT * 2)   // 9216 B per 64x64 bf16 tile
#define LAW_S 132     // stats AW smem stride (floats, 16B-mult, 528B)
#define LAW_A 68      // av AW smem stride (floats, 272B)

// -------- scratch (device globals; no allocation allowed) --------
__device__ __align__(256) __nv_bfloat16 g_xq_h[(size_t)BB * NN * CC];
__device__ __align__(256) __nv_bfloat16 g_xq_l[(size_t)BB * NN * CC];
__device__ __align__(256) __nv_bfloat16 g_xk_h[(size_t)BB * SS * CC];
__device__ __align__(256) __nv_bfloat16 g_xk_l[(size_t)BB * SS * CC];
__device__ __align__(256) __nv_bfloat16 g_xv_h[(size_t)BB * SS * CC];
__device__ __align__(256) __nv_bfloat16 g_xv_l[(size_t)BB * SS * CC];
__device__ __align__(256) __nv_bfloat16 g_wq_h[(size_t)CC * CC];
__device__ __align__(256) __nv_bfloat16 g_wq_l[(size_t)CC * CC];
__device__ __align__(256) __nv_bfloat16 g_wk_h[(size_t)CC * CC];
__device__ __align__(256) __nv_bfloat16 g_wk_l[(size_t)CC * CC];
__device__ __align__(256) __nv_bfloat16 g_wv_h[(size_t)CC * CC];
__device__ __align__(256) __nv_bfloat16 g_wv_l[(size_t)CC * CC];
__device__ __align__(256) __nv_bfloat16 g_wo_h[(size_t)CC * CC];
__device__ __align__(256) __nv_bfloat16 g_wo_l[(size_t)CC * CC];
__device__ __align__(256) __nv_bfloat16 g_Qh[(size_t)BB * HH * NN * DD];
__device__ __align__(256) __nv_bfloat16 g_Ql[(size_t)BB * HH * NN * DD];
__device__ __align__(256) __nv_bfloat16 g_Kh[(size_t)BB * HH * SS * DD];
__device__ __align__(256) __nv_bfloat16 g_Kl[(size_t)BB * HH * SS * DD];
__device__ __align__(256) __nv_bfloat16 g_Vh[(size_t)BB * HH * SS * DD];
__device__ __align__(256) __nv_bfloat16 g_Vl[(size_t)BB * HH * SS * DD];
__device__ __align__(256) __nv_bfloat16 g_AOh[(size_t)BB * NN * CC];
__device__ __align__(256) __nv_bfloat16 g_AOl[(size_t)BB * NN * CC];
__device__ float g_lse[BB * HH * NN];
__device__ float g_isu[BB * HH * NN];

// ============================================================================
// helpers
// ============================================================================
__device__ __forceinline__ uint32_t smem_u32(const void* p) {
    uint32_t a;
    asm("{ .reg .u64 t; cvta.to.shared.u64 t, %1; cvt.u32.u64 %0, t; }" : "=r"(a) : "l"(p));
    return a;
}
__device__ __forceinline__ void mma_bf16(float* c, const uint32_t* a, const uint32_t* b) {
    asm volatile("mma.sync.aligned.m16n8k16.row.col.f32.bf16.bf16.f32 "
        "{%0,%1,%2,%3}, {%4,%5,%6,%7}, {%8,%9}, {%0,%1,%2,%3};"
        : "+f"(c[0]), "+f"(c[1]), "+f"(c[2]), "+f"(c[3])
        : "r"(a[0]), "r"(a[1]), "r"(a[2]), "r"(a[3]), "r"(b[0]), "r"(b[1]));
}
__device__ __forceinline__ void ldsm_x4(uint32_t* r, uint32_t a) {
    asm volatile("ldmatrix.sync.aligned.m8n8.x4.shared.b16 {%0,%1,%2,%3}, [%4];"
        : "=r"(r[0]), "=r"(r[1]), "=r"(r[2]), "=r"(r[3]) : "r"(a));
}
__device__ __forceinline__ void ldsm_x2(uint32_t* r, uint32_t a) {
    asm volatile("ldmatrix.sync.aligned.m8n8.x2.shared.b16 {%0,%1}, [%2];"
        : "=r"(r[0]), "=r"(r[1]) : "r"(a));
}
__device__ __forceinline__ void ldsm_x2t(uint32_t* r, uint32_t a) {
    asm volatile("ldmatrix.sync.aligned.m8n8.x2.trans.shared.b16 {%0,%1}, [%2];"
        : "=r"(r[0]), "=r"(r[1]) : "r"(a));
}
#define CPA16(dst, src) \
    asm volatile("cp.async.cg.shared.global [%0], [%1], 16;" :: "r"(dst), "l"(src) : "memory")
#define CPA_COMMIT() asm volatile("cp.async.commit_group;" ::: "memory")
#define CPA_WAIT(n)  asm volatile("cp.async.wait_group %0;" :: "n"(n) : "memory")

__device__ __forceinline__ uint32_t packbf(float x, float y) {
    __nv_bfloat162 t = __halves2bfloat162(__float2bfloat16(x), __float2bfloat16(y));
    return *(uint32_t*)&t;
}
__device__ __forceinline__ float bflo(float x) {
    return x - __bfloat162float(__float2bfloat16(x));
}

// ============================================================================
// fp32 -> bf16 hi/lo split; z selects among up to 4 tensors
// ============================================================================
__device__ __forceinline__ void split_one(const float* __restrict__ x,
                                          __nv_bfloat16* __restrict__ hi,
                                          __nv_bfloat16* __restrict__ lo, int i) {
    float4 v = *(const float4*)(x + (size_t)i * 4);
    __nv_bfloat16 h0 = __float2bfloat16(v.x), h1 = __float2bfloat16(v.y);
    __nv_bfloat16 h2 = __float2bfloat16(v.z), h3 = __float2bfloat16(v.w);
    *(__nv_bfloat162*)(hi + (size_t)i * 4)     = __halves2bfloat162(h0, h1);
    *(__nv_bfloat162*)(hi + (size_t)i * 4 + 2) = __halves2bfloat162(h2, h3);
    *(__nv_bfloat162*)(lo + (size_t)i * 4)     = __halves2bfloat162(
        __float2bfloat16(v.x - __bfloat162float(h0)), __float2bfloat16(v.y - __bfloat162float(h1)));
    *(__nv_bfloat162*)(lo + (size_t)i * 4 + 2) = __halves2bfloat162(
        __float2bfloat16(v.z - __bfloat162float(h2)), __float2bfloat16(v.w - __bfloat162float(h3)));
}

__global__ void split_x3(const float* __restrict__ xq, const float* __restrict__ xk,
                         const float* __restrict__ xv, int n4) {
    int i = blockIdx.x * blockDim.x + threadIdx.x;
    if (i >= n4) return;
    if (blockIdx.z == 0)      split_one(xq, g_xq_h, g_xq_l, i);
    else if (blockIdx.z == 1) split_one(xk, g_xk_h, g_xk_l, i);
    else                      split_one(xv, g_xv_h, g_xv_l, i);
}
__global__ void split_w4(const float* __restrict__ wq, const float* __restrict__ wk,
                         const float* __restrict__ wv, const float* __restrict__ wo, int n4) {
    int i = blockIdx.x * blockDim.x + threadIdx.x;
    if (i >= n4) return;
    if (blockIdx.z == 0)      split_one(wq, g_wq_h, g_wq_l, i);
    else if (blockIdx.z == 1) split_one(wk, g_wk_h, g_wk_l, i);
    else if (blockIdx.z == 2) split_one(wv, g_wv_h, g_wv_l, i);
    else                      split_one(wo, g_wo_h, g_wo_l, i);
}

// ============================================================================
// shared GEMM mainloop (unchanged): c[2][4][4] += X . W^T, 3-term split
// ============================================================================
__device__ __forceinline__ void gemm_mainloop(
    const __nv_bfloat16* __restrict__ Xh, const __nv_bfloat16* __restrict__ Xl,
    const __nv_bfloat16* __restrict__ Wh, const __nv_bfloat16* __restrict__ Wl,
    int m0, int n0, uint32_t s0, int tid, int lane, int wm, int wn,
    float c[2][4][4]) {
    auto issue = [&](int ch, int buf) {
        const size_t xb = (size_t)m0 * CC + ch * 64;
        const size_t wb = (size_t)n0 * CC + ch * 64;
        const uint32_t base = s0 + buf * 4 * TILEB;
        #pragma unroll
        for (int t = 0; t < 2; t++) {
            const int id = tid + NT * t, row = id >> 3, seg = id & 7;
            const uint32_t doff = (uint32_t)(row * LDT + seg * 8) * 2;
            const size_t sx = xb + (size_t)row * CC + seg * 8;
            const size_t sw = wb + (size_t)row * CC + seg * 8;
            CPA16(base + 0 * TILEB + doff, Xh + sx);
            CPA16(base + 1 * TILEB + doff, Xl + sx);
            CPA16(base + 2 * TILEB + doff, Wh + sw);
            CPA16(base + 3 * TILEB + doff, Wl + sw);
        }
    };
    issue(0, 0); CPA_COMMIT(); CPA_WAIT(0);
    __syncthreads();
    int buf = 0;
    for (int ch = 0; ch < 12; ch++) {
        if (ch < 11) { issue(ch + 1, buf ^ 1); CPA_COMMIT(); }
        const uint32_t aH = s0 + buf * 4 * TILEB, aL = aH + TILEB;
        const uint32_t bH = aL + TILEB, bL = bH + TILEB;
        #pragma unroll
        for (int ks = 0; ks < 4; ks++) {
            uint32_t ah[2][4], al[2][4], bh[4][2], bl[4][2];
            #pragma unroll
            for (int mi = 0; mi < 2; mi++) {
                uint32_t off = ((wm * 32 + mi * 16 + (lane & 15)) * LDT + ks * 16 + (lane >> 4) * 8) * 2;
                ldsm_x4(ah[mi], aH + off);
                ldsm_x4(al[mi], aL + off);
            }
            #pragma unroll
            for (int ni = 0; ni < 4; ni++) {
                uint32_t off = ((wn * 32 + ni * 8 + (lane & 7)) * LDT + ks * 16 + ((lane >> 3) & 1) * 8) * 2;
                ldsm_x2(bh[ni], bH + off);
                ldsm_x2(bl[ni], bL + off);
            }
            #pragma unroll
            for (int mi = 0; mi < 2; mi++)
                #pragma unroll
                for (int ni = 0; ni < 4; ni++) {
                    mma_bf16(c[mi][ni], ah[mi], bh[ni]);
                    mma_bf16(c[mi][ni], ah[mi], bl[ni]);
                    mma_bf16(c[mi][ni], al[mi], bh[ni]);
                }
        }
        CPA_WAIT(0);
        __syncthreads();
        buf ^= 1;
    }
}

// QKV projections merged: grid.z selects tensor; head-major pre-split output
__global__ void __launch_bounds__(NT, 1) tc_gemm_qkv() {
    extern __shared__ char sm[];
    const uint32_t s0 = smem_u32(sm);
    const int tid = threadIdx.x, lane = tid & 31, wid = tid >> 5;
    const int wm = wid & 3, wn = wid >> 2;
    const int m0 = blockIdx.y * 128, n0 = blockIdx.x * 128, z = blockIdx.z;
    const __nv_bfloat16 *Xh, *Xl, *Wh, *Wl;
    __nv_bfloat16 *Yh, *Yl;
    if (z == 0)      { Xh = g_xq_h; Xl = g_xq_l; Wh = g_wq_h; Wl = g_wq_l; Yh = g_Qh; Yl = g_Ql; }
    else if (z == 1) { Xh = g_xk_h; Xl = g_xk_l; Wh = g_wk_h; Wl = g_wk_l; Yh = g_Kh; Yl = g_Kl; }
    else             { Xh = g_xv_h; Xl = g_xv_l; Wh = g_wv_h; Wl = g_wv_l; Yh = g_Vh; Yl = g_Vl; }

    float c[2][4][4] = {};
    gemm_mainloop(Xh, Xl, Wh, Wl, m0, n0, s0, tid, lane, wm, wn, c);

    const int qr = lane >> 2, qc = (lane & 3) * 2;
    #pragma unroll
    for (int mi = 0; mi < 2; mi++)
        #pragma unroll
        for (int ni = 0; ni < 4; ni++) {
            const int rowg = m0 + wm * 32 + mi * 16 + qr;
            const int b = rowg >> 10, r = rowg & 1023;
            const int col = n0 + wn * 32 + ni * 8 + qc;
            const int h = col >> 6, d = col & 63;
            const size_t o0 = ((size_t)(b * HH + h) * NN + r) * DD + d;
            const size_t o1 = o0 + (size_t)8 * DD;
            float x0 = c[mi][ni][0], x1 = c[mi][ni][1];
            float x2 = c[mi][ni][2], x3 = c[mi][ni][3];
            *(uint32_t*)(Yh + o0) = packbf(x0, x1);
            *(uint32_t*)(Yh + o1) = packbf(x2, x3);
            *(uint32_t*)(Yl + o0) = packbf(bflo(x0), bflo(x1));
            *(uint32_t*)(Yl + o1) = packbf(bflo(x2), bflo(x3));
        }
}

// output projection: AO @ Wo + bo -> fp32
__global__ void __launch_bounds__(NT, 1) tc_gemm_out(const float* __restrict__ bias,
                                                     float* __restrict__ Yf) {
    extern __shared__ char sm[];
    const uint32_t s0 = smem_u32(sm);
    const int tid = threadIdx.x, lane = tid & 31, wid = tid >> 5;
    const int wm = wid & 3, wn = wid >> 2;
    const int m0 = blockIdx.y * 128, n0 = blockIdx.x * 128;

    float c[2][4][4] = {};
    gemm_mainloop(g_AOh, g_AOl, g_wo_h, g_wo_l, m0, n0, s0, tid, lane, wm, wn, c);

    const int qr = lane >> 2, qc = (lane & 3) * 2;
    #pragma unroll
    for (int mi = 0; mi < 2; mi++)
        #pragma unroll
        for (int ni = 0; ni < 4; ni++) {
            const int row = m0 + wm * 32 + mi * 16 + qr;
            const int col = n0 + wn * 32 + ni * 8 + qc;
            *(float2*)(Yf + (size_t)row * CC + col) =
                make_float2(c[mi][ni][0] + bias[col], c[mi][ni][1] + bias[col + 1]);
            *(float2*)(Yf + (size_t)(row + 8) * CC + col) =
                make_float2(c[mi][ni][2] + bias[col], c[mi][ni][3] + bias[col + 1]);
        }
}

// copy a head-major 128x64 bf16 tile pair (hi,lo) to smem via cp.async
__device__ __forceinline__ void cpa_tile_pair(uint32_t dhi, uint32_t dlo,
                                              const __nv_bfloat16* __restrict__ shi,
                                              const __nv_bfloat16* __restrict__ slo,
                                              size_t base, int tid) {
    #pragma unroll
    for (int t = 0; t < 2; t++) {
        const int id = tid + NT * t, row = id >> 3, seg = id & 7;
        const uint32_t doff = (uint32_t)(row * LDT + seg * 8) * 2;
        const size_t s = base + (size_t)row * 64 + seg * 8;
        CPA16(dhi + doff, shi + s);
        CPA16(dlo + doff, slo + s);
    }
}
// 64-row variant (one iter per thread)
__device__ __forceinline__ void cpa_tile_pair64(uint32_t dhi, uint32_t dlo,
                                                const __nv_bfloat16* __restrict__ shi,
                                                const __nv_bfloat16* __restrict__ slo,
                                                size_t base, int tid) {
    const int row = tid >> 3, seg = tid & 7;
    const uint32_t doff = (uint32_t)(row * LDT + seg * 8) * 2;
    const size_t s = base + (size_t)row * 64 + seg * 8;
    CPA16(dhi + doff, shi + s);
    CPA16(dlo + doff, slo + s);
}

// ============================================================================
// Pass 1: ssum/usum with AW prefetched into smem (single-buffer, early issue).
// smem: Q(2) + K dbuf(4) + AW(67584) + red = 182272 B.
// ============================================================================
__global__ void __launch_bounds__(NT, 1) attn_stats(const float* __restrict__ AW) {
    extern __shared__ char sm[];
    const uint32_t s0 = smem_u32(sm);
    const uint32_t sQH = s0, sQL = s0 + TILEB;
    const uint32_t sAW = s0 + 6 * TILEB;
    float* awp = (float*)(sm + 6 * TILEB);
    float* redS = (float*)(sm + 6 * TILEB + 128 * LAW_S * 4);
    float* redU = redS + 4 * 128;

    const int tid = threadIdx.x, lane = tid & 31, wid = tid >> 5;
    const int wm = wid & 3, wn = wid >> 2;
    const int bh = blockIdx.y;
    const int q0 = blockIdx.x * 128;
    const int qr = lane >> 2, qc = (lane & 3) * 2;

    const size_t qbase = ((size_t)bh * NN + q0) * DD;
    const size_t kbase0 = (size_t)bh * SS * DD;
    const size_t awrow0 = ((size_t)bh * NN + q0) * SS;

    cpa_tile_pair(sQH, sQL, g_Qh, g_Ql, qbase, tid);
    cpa_tile_pair(s0 + 2 * TILEB, s0 + 3 * TILEB, g_Kh, g_Kl, kbase0, tid);
    CPA_COMMIT(); CPA_WAIT(0);
    __syncthreads();

    float ssum[4] = {}, usum[4] = {};

    for (int sc = 0; sc < 8; sc++) {
        const int buf = sc & 1;
        // issue AW(sc) tile copy (group 1)
        {
            const size_t ab = awrow0 + sc * 128;
            #pragma unroll
            for (int t = 0; t < 8; t++) {
                const int id = tid + NT * t, row = id >> 5, seg = id & 31;
                CPA16(sAW + (uint32_t)(row * LAW_S + seg * 4) * 4,
                      AW + ab + (size_t)row * SS + seg * 4);
            }
            CPA_COMMIT();
        }
        if (sc < 7) {
            cpa_tile_pair(s0 + (2 + 2 * (buf ^ 1)) * TILEB, s0 + (3 + 2 * (buf ^ 1)) * TILEB,
                          g_Kh, g_Kl, kbase0 + (size_t)(sc + 1) * 128 * DD, tid);
            CPA_COMMIT();
        }
        const uint32_t kH = s0 + (2 + 2 * buf) * TILEB, kL = kH + TILEB;

        float c[2][4][4] = {};
        #pragma unroll
        for (int ks = 0; ks < 4; ks++) {
            uint32_t ah[2][4], al[2][4], bh2[4][2], bl2[4][2];
            #pragma unroll
            for (int mi = 0; mi < 2; mi++) {
                uint32_t off = ((wm * 32 + mi * 16 + (lane & 15)) * LDT + ks * 16 + (lane >> 4) * 8) * 2;
                ldsm_x4(ah[mi], sQH + off);
                ldsm_x4(al[mi], sQL + off);
            }
            #pragma unroll
            for (int ni = 0; ni < 4; ni++) {
                uint32_t off = ((wn * 32 + ni * 8 + (lane & 7)) * LDT + ks * 16 + ((lane >> 3) & 1) * 8) * 2;
                ldsm_x2(bh2[ni], kH + off);
                ldsm_x2(bl2[ni], kL + off);
            }
            #pragma unroll
            for (int mi = 0; mi < 2; mi++)
                #pragma unroll
                for (int ni = 0; ni < 4; ni++) {
                    mma_bf16(c[mi][ni], ah[mi], bh2[ni]);
                    mma_bf16(c[mi][ni], ah[mi], bl2[ni]);
                    mma_bf16(c[mi][ni], al[mi], bh2[ni]);
                }
        }

        if (sc < 7) { CPA_WAIT(1); } else { CPA_WAIT(0); }
        __syncthreads();   // AW tile visible

        #pragma unroll
        for (int mi = 0; mi < 2; mi++) {
            const int row0 = wm * 32 + mi * 16 + qr;
            #pragma unroll
            for (int ni = 0; ni < 4; ni++) {
                const int col = wn * 32 + ni * 8 + qc;
                float2 aw0 = *(float2*)(awp + row0 * LAW_S + col);
                float2 aw1 = *(float2*)(awp + (row0 + 8) * LAW_S + col);
                float sc00 = c[mi][ni][0] * SCALEF, sc01 = c[mi][ni][1] * SCALEF;
                float sc10 = c[mi][ni][2] * SCALEF, sc11 = c[mi][ni][3] * SCALEF;
                ssum[mi * 2]     += __expf(sc00) + __expf(sc01);
                ssum[mi * 2 + 1] += __expf(sc10) + __expf(sc11);
                usum[mi * 2]     += __expf(sc00 + aw0.x) + __expf(sc01 + aw0.y);
                usum[mi * 2 + 1] += __expf(sc10 + aw1.x) + __expf(sc11 + aw1.y);
            }
        }
        CPA_WAIT(0);
        __syncthreads();   // K buffer swap + AW reuse safe
    }

    #pragma unroll
    for (int sl = 0; sl < 4; sl++) {
        ssum[sl] += __shfl_xor_sync(~0u, ssum[sl], 1);
        ssum[sl] += __shfl_xor_sync(~0u, ssum[sl], 2);
        usum[sl] += __shfl_xor_sync(~0u, usum[sl], 1);
        usum[sl] += __shfl_xor_sync(~0u, usum[sl], 2);
    }
    if ((lane & 3) == 0) {
        #pragma unroll
        for (int sl = 0; sl < 4; sl++) {
            const int row = wm * 32 + (sl >> 1) * 16 + qr + 8 * (sl & 1);
            redS[wn * 128 + row] = ssum[sl];
            redU[wn * 128 + row] = usum[sl];
        }
    }
    __syncthreads();
    if (tid < 128) {
        float st = redS[tid] + redS[128 + tid] + redS[256 + tid] + redS[384 + tid];
        float ut = redU[tid] + redU[128 + tid] + redU[256 + tid] + redU[384 + tid];
        const int gi = bh * NN + q0 + tid;
        g_lse[gi] = __logf(st);
        g_isu[gi] = 1.0f / ut;
    }
}

// ============================================================================
// Pass 2: 64-column s-chunks (16 chunks). AW+V prefetch, K double-buffered.
// smem: Q(36864) K(36864) V(18432) P(36864) AW(34816) = 163840 B.
// ============================================================================
__global__ void __launch_bounds__(NT, 1) attn_av(const float* __restrict__ AW,
                                                 float* __restrict__ LOGOUT) {
    extern __shared__ char sm[];
    const uint32_t s0 = smem_u32(sm);
    const uint32_t sQH = s0, sQL = s0 + TILEB;
    const uint32_t kBase = s0 + 2 * TILEB;                // 2 bufs x (hi,lo) 64-row tiles
    const uint32_t sVH = s0 + 2 * TILEB + 4 * KTILEB;     // 73728
    const uint32_t sVL = sVH + KTILEB;
    const uint32_t pH = sVL + KTILEB;                     // 92160
    const uint32_t pL = pH + 128 * LDP2 * 2;
    const uint32_t sAW = pL + 128 * LDP2 * 2;             // 129024
    float* awp = (float*)(sm + (sAW - s0));

    const int tid = threadIdx.x, lane = tid & 31, wid = tid >> 5;
    const int wm = wid & 3, wn = wid >> 2;
    const int bh = blockIdx.y;
    const int q0 = blockIdx.x * 128;
    const int qr = lane >> 2, qc = (lane & 3) * 2;

    const size_t qbase = ((size_t)bh * NN + q0) * DD;
    const size_t kvbase = (size_t)bh * SS * DD;
    const size_t awrow0 = ((size_t)bh * NN + q0) * SS;

    cpa_tile_pair(sQH, sQL, g_Qh, g_Ql, qbase, tid);
    cpa_tile_pair64(kBase, kBase + KTILEB, g_Kh, g_Kl, kvbase, tid);
    CPA_COMMIT(); CPA_WAIT(0);
    __syncthreads();

    float lse_r[4], isu_r[4];
    #pragma unroll
    for (int sl = 0; sl < 4; sl++) {
        const int row = q0 + wm * 32 + (sl >> 1) * 16 + qr + 8 * (sl & 1);
        lse_r[sl] = g_lse[bh * NN + row];
        isu_r[sl] = g_isu[bh * NN + row];
    }

    float c2[2][2][4] = {};

    for (int sc = 0; sc < 16; sc++) {
        const int buf = sc & 1;
        // group 1: AW(sc) + V(sc)
        {
            const size_t ab = awrow0 + sc * 64;
            #pragma unroll
            for (int t = 0; t < 4; t++) {
                const int id = tid + NT * t, row = id >> 4, seg = id & 15;
                CPA16(sAW + (uint32_t)(row * LAW_A + seg * 4) * 4,
                      AW + ab + (size_t)row * SS + seg * 4);
            }
            cpa_tile_pair64(sVH, sVL, g_Vh, g_Vl, kvbase + (size_t)sc * 64 * DD, tid);
            CPA_COMMIT();
        }
        if (sc < 15) {
            const uint32_t kb = kBase + (buf ^ 1) * 2 * KTILEB;
            cpa_tile_pair64(kb, kb + KTILEB, g_Kh, g_Kl, kvbase + (size_t)(sc + 1) * 64 * DD, tid);
            CPA_COMMIT();
        }
        const uint32_t kH = kBase + buf * 2 * KTILEB, kL = kH + KTILEB;

        // ---- QK: 128x64 tile; warp (wm, wn), 32x16
        float c[2][2][4] = {};
        #pragma unroll
        for (int ks = 0; ks < 4; ks++) {
            uint32_t ah[2][4], al[2][4], bh2[2][2], bl2[2][2];
            #pragma unroll
            for (int mi = 0; mi < 2; mi++) {
                uint32_t off = ((wm * 32 + mi * 16 + (lane & 15)) * LDT + ks * 16 + (lane >> 4) * 8) * 2;
                ldsm_x4(ah[mi], sQH + off);
                ldsm_x4(al[mi], sQL + off);
            }
            #pragma unroll
            for (int ni = 0; ni < 2; ni++) {
                uint32_t off = ((wn * 16 + ni * 8 + (lane & 7)) * LDT + ks * 16 + ((lane >> 3) & 1) * 8) * 2;
                ldsm_x2(bh2[ni], kH + off);
                ldsm_x2(bl2[ni], kL + off);
            }
            #pragma unroll
            for (int mi = 0; mi < 2; mi++)
                #pragma unroll
                for (int ni = 0; ni < 2; ni++) {
                    mma_bf16(c[mi][ni], ah[mi], bh2[ni]);
                    mma_bf16(c[mi][ni], ah[mi], bl2[ni]);
                    mma_bf16(c[mi][ni], al[mi], bh2[ni]);
                }
        }

        if (sc < 15) { CPA_WAIT(1); } else { CPA_WAIT(0); }
        __syncthreads();   // AW + V visible

        // ---- softmax + logits + split-P store (AW from smem)
        #pragma unroll
        for (int mi = 0; mi < 2; mi++) {
            const int prow0 = wm * 32 + mi * 16 + qr;
            const size_t rbb = ((size_t)bh * NN + q0 + prow0) * SS + sc * 64;
            #pragma unroll
            for (int ni = 0; ni < 2; ni++) {
                const int col = wn * 16 + ni * 8 + qc;
                const size_t rb = rbb + col;
                float2 aw0 = *(float2*)(awp + prow0 * LAW_A + col);
                float2 aw1 = *(float2*)(awp + (prow0 + 8) * LAW_A + col);
                float u00 = fmaf(c[mi][ni][0], SCALEF, aw0.x);
                float u01 = fmaf(c[mi][ni][1], SCALEF, aw0.y);
                float u10 = fmaf(c[mi][ni][2], SCALEF, aw1.x);
                float u11 = fmaf(c[mi][ni][3], SCALEF, aw1.y);
                const int sl0 = mi * 2, sl1 = mi * 2 + 1;
                *(float2*)(LOGOUT + rb) = make_float2(u00 - lse_r[sl0], u01 - lse_r[sl0]);
                *(float2*)(LOGOUT + rb + (size_t)8 * SS) = make_float2(u10 - lse_r[sl1], u11 - lse_r[sl1]);
                float p00 = __expf(u00) * isu_r[sl0], p01 = __expf(u01) * isu_r[sl0];
                float p10 = __expf(u10) * isu_r[sl1], p11 = __expf(u11) * isu_r[sl1];
                *(uint32_t*)(sm + (pH - s0) + (prow0 * LDP2 + col) * 2)       = packbf(p00, p01);
                *(uint32_t*)(sm + (pH - s0) + ((prow0 + 8) * LDP2 + col) * 2) = packbf(p10, p11);
                *(uint32_t*)(sm + (pL - s0) + (prow0 * LDP2 + col) * 2)       = packbf(bflo(p00), bflo(p01));
                *(uint32_t*)(sm + (pL - s0) + ((prow0 + 8) * LDP2 + col) * 2) = packbf(bflo(p10), bflo(p11));
            }
        }
        __syncthreads();   // P visible

        // ---- PV: O[128x64] += P[128x64] @ V[64x64], warp tile 32x16
        #pragma unroll
        for (int ksp = 0; ksp < 4; ksp++) {
            uint32_t pa[2][4], pe[2][4], vh[2][2], vl[2][2];
            #pragma unroll
            for (int mi = 0; mi < 2; mi++) {
                uint32_t off = ((wm * 32 + mi * 16 + (lane & 15)) * LDP2 + ksp * 16 + (lane >> 4) * 8) * 2;
                ldsm_x4(pa[mi], pH + off);
                ldsm_x4(pe[mi], pL + off);
            }
            #pragma unroll
            for (int nj = 0; nj < 2; nj++) {
                uint32_t off = ((ksp * 16 + (lane & 15)) * LDT + wn * 16 + nj * 8) * 2;
                ldsm_x2t(vh[nj], sVH + off);
                ldsm_x2t(vl[nj], sVL + off);
            }
            #pragma unroll
            for (int mi = 0; mi < 2; mi++)
                #pragma unroll
                for (int nj = 0; nj < 2; nj++) {
                    mma_bf16(c2[mi][nj], pa[mi], vh[nj]);
                    mma_bf16(c2[mi][nj], pa[mi], vl[nj]);
                    mma_bf16(c2[mi][nj], pe[mi], vh[nj]);
                }
        }
        CPA_WAIT(0);
        __syncthreads();   // K swap + V/AW/P reuse safe
    }

    const int b = bh / HH, h = bh % HH;
    #pragma unroll
    for (int mi = 0; mi < 2; mi++)
        #pragma unroll
        for (int nj = 0; nj < 2; nj++) {
            const int row = q0 + wm * 32 + mi * 16 + qr;
            const int col = h * DD + wn * 16 + nj * 8 + qc;
            const size_t o0 = (size_t)(b * NN + row) * CC + col;
            const size_t o1 = (size_t)(b * NN + row + 8) * CC + col;
            float x0 = c2[mi][nj][0], x1 = c2[mi][nj][1];
            float x2 = c2[mi][nj][2], x3 = c2[mi][nj][3];
            *(uint32_t*)(g_AOh + o0) = packbf(x0, x1);
            *(uint32_t*)(g_AOh + o1) = packbf(x2, x3);
            *(uint32_t*)(g_AOl + o0) = packbf(bflo(x0), bflo(x1));
            *(uint32_t*)(g_AOl + o1) = packbf(bflo(x2), bflo(x3));
        }
}

// ============================================================================
extern "C" void kernel_launch(void* const* d_in, const int* in_sizes, int n_in,
                              void* d_out, int out_size) {
    const float* query = (const float*)d_in[0];
    const float* key_  = (const float*)d_in[1];
    const float* value = (const float*)d_in[2];
    const float* aw    = (const float*)d_in[3];
    const float* Wq    = (const float*)d_in[4];
    const float* Wk    = (const float*)d_in[5];
    const float* Wv    = (const float*)d_in[6];
    const float* Wo    = (const float*)d_in[7];
    const float* bo    = (const float*)d_in[8];

    float* out    = (float*)d_out;                       // [B,N,C]
    float* logout = out + (size_t)BB * NN * CC;          // [B,H,N,S]

    const int smem_gemm  = 8 * TILEB;                              // 147456
    const int smem_stats = 6 * TILEB + 128 * LAW_S * 4 + 4096;     // 182272
    const int smem_av    = 2 * TILEB + 4 * KTILEB + 2 * KTILEB
                         + 2 * (128 * LDP2 * 2) + 128 * LAW_A * 4; // 163840
    cudaFuncSetAttribute(tc_gemm_qkv, cudaFuncAttributeMaxDynamicSharedMemorySize, smem_gemm);
    cudaFuncSetAttribute(tc_gemm_out, cudaFuncAttributeMaxDynamicSharedMemorySize, smem_gemm);
    cudaFuncSetAttribute(attn_stats,  cudaFuncAttributeMaxDynamicSharedMemorySize, smem_stats);
    cudaFuncSetAttribute(attn_av,     cudaFuncAttributeMaxDynamicSharedMemorySize, smem_av);

    const int nX4 = (BB * NN * CC) / 4;
    const int nW4 = (CC * CC) / 4;
    dim3 gsx((nX4 + 255) / 256, 1, 3);
    dim3 gsw((nW4 + 255) / 256, 1, 4);
    dim3 gqkv(CC / 128, (BB * NN) / 128, 3);   // 6 x 64 x 3
    dim3 gp(CC / 128, (BB * NN) / 128);        // 6 x 64
    dim3 ga(NN / 128, BB * HH);                // 8 x 96

    split_x3<<<gsx, 256>>>(query, key_, value, nX4);
    split_w4<<<gsw, 256>>>(Wq, Wk, Wv, Wo, nW4);
    tc_gemm_qkv<<<gqkv, NT, smem_gemm>>>();
    attn_stats<<<ga, NT, smem_stats>>>(aw);
    attn_av<<<ga, NT, smem_av>>>(aw, logout);
    tc_gemm_out<<<gp, NT, smem_gemm>>>(bo, out);
}

// round 12
// speedup vs baseline: 1.0589x; 1.0589x over previous
#include <cuda_runtime.h>
#include <cuda_bf16.h>
#include <math.h>
#include <stdint.h>

#define BB 8
#define NN 1024
#define SS 1024
#define CC 768
#define HH 12
#define DD 64
#define SCALEF 0.125f

#define LDT 72        // bf16 elems per 64-wide tile row (144B, conflict-free)
#define LDP 136       // bf16 elems per 128-wide P tile row (272B)
#define NT 512
#define TILEB (128 * LDT * 2)   // 18432 B per 128x64 bf16 tile
#define QTILEB (64 * LDT * 2)   // 9216 B per 64x64 bf16 tile
#define PTILEB (128 * LDP * 2)  // 34816 B per 128x128 bf16 tile

// -------- scratch (device globals; no allocation allowed) --------
__device__ __align__(256) __nv_bfloat16 g_xq_h[(size_t)BB * NN * CC];
__device__ __align__(256) __nv_bfloat16 g_xq_l[(size_t)BB * NN * CC];
__device__ __align__(256) __nv_bfloat16 g_xk_h[(size_t)BB * SS * CC];
__device__ __align__(256) __nv_bfloat16 g_xk_l[(size_t)BB * SS * CC];
__device__ __align__(256) __nv_bfloat16 g_xv_h[(size_t)BB * SS * CC];
__device__ __align__(256) __nv_bfloat16 g_xv_l[(size_t)BB * SS * CC];
__device__ __align__(256) __nv_bfloat16 g_wq_h[(size_t)CC * CC];
__device__ __align__(256) __nv_bfloat16 g_wq_l[(size_t)CC * CC];
__device__ __align__(256) __nv_bfloat16 g_wk_h[(size_t)CC * CC];
__device__ __align__(256) __nv_bfloat16 g_wk_l[(size_t)CC * CC];
__device__ __align__(256) __nv_bfloat16 g_wv_h[(size_t)CC * CC];
__device__ __align__(256) __nv_bfloat16 g_wv_l[(size_t)CC * CC];
__device__ __align__(256) __nv_bfloat16 g_wo_h[(size_t)CC * CC];
__device__ __align__(256) __nv_bfloat16 g_wo_l[(size_t)CC * CC];
__device__ __align__(256) __nv_bfloat16 g_Qh[(size_t)BB * HH * NN * DD];
__device__ __align__(256) __nv_bfloat16 g_Ql[(size_t)BB * HH * NN * DD];
__device__ __align__(256) __nv_bfloat16 g_Kh[(size_t)BB * HH * SS * DD];
__device__ __align__(256) __nv_bfloat16 g_Kl[(size_t)BB * HH * SS * DD];
__device__ __align__(256) __nv_bfloat16 g_Vh[(size_t)BB * HH * SS * DD];
__device__ __align__(256) __nv_bfloat16 g_Vl[(size_t)BB * HH * SS * DD];
__device__ __align__(256) __nv_bfloat16 g_AOh[(size_t)BB * NN * CC];
__device__ __align__(256) __nv_bfloat16 g_AOl[(size_t)BB * NN * CC];
__device__ float g_lse[BB * HH * NN];
__device__ float g_isu[BB * HH * NN];

// ============================================================================
// helpers
// ============================================================================
__device__ __forceinline__ uint32_t smem_u32(const void* p) {
    uint32_t a;
    asm("{ .reg .u64 t; cvta.to.shared.u64 t, %1; cvt.u32.u64 %0, t; }" : "=r"(a) : "l"(p));
    return a;
}
__device__ __forceinline__ void mma_bf16(float* c, const uint32_t* a, const uint32_t* b) {
    asm volatile("mma.sync.aligned.m16n8k16.row.col.f32.bf16.bf16.f32 "
        "{%0,%1,%2,%3}, {%4,%5,%6,%7}, {%8,%9}, {%0,%1,%2,%3};"
        : "+f"(c[0]), "+f"(c[1]), "+f"(c[2]), "+f"(c[3])
        : "r"(a[0]), "r"(a[1]), "r"(a[2]), "r"(a[3]), "r"(b[0]), "r"(b[1]));
}
__device__ __forceinline__ void ldsm_x4(uint32_t* r, uint32_t a) {
    asm volatile("ldmatrix.sync.aligned.m8n8.x4.shared.b16 {%0,%1,%2,%3}, [%4];"
        : "=r"(r[0]), "=r"(r[1]), "=r"(r[2]), "=r"(r[3]) : "r"(a));
}
__device__ __forceinline__ void ldsm_x2(uint32_t* r, uint32_t a) {
    asm volatile("ldmatrix.sync.aligned.m8n8.x2.shared.b16 {%0,%1}, [%2];"
        : "=r"(r[0]), "=r"(r[1]) : "r"(a));
}
__device__ __forceinline__ void ldsm_x2t(uint32_t* r, uint32_t a) {
    asm volatile("ldmatrix.sync.aligned.m8n8.x2.trans.shared.b16 {%0,%1}, [%2];"
        : "=r"(r[0]), "=r"(r[1]) : "r"(a));
}
#define CPA16(dst, src) \
    asm volatile("cp.async.cg.shared.global [%0], [%1], 16;" :: "r"(dst), "l"(src) : "memory")
#define CPA_COMMIT() asm volatile("cp.async.commit_group;" ::: "memory")
#define CPA_WAIT(n)  asm volatile("cp.async.wait_group %0;" :: "n"(n) : "memory")

__device__ __forceinline__ uint32_t packbf(float x, float y) {
    __nv_bfloat162 t = __halves2bfloat162(__float2bfloat16(x), __float2bfloat16(y));
    return *(uint32_t*)&t;
}
__device__ __forceinline__ float bflo(float x) {
    return x - __bfloat162float(__float2bfloat16(x));
}

// ============================================================================
// fp32 -> bf16 hi/lo split; z selects among up to 4 tensors
// ============================================================================
__device__ __forceinline__ void split_one(const float* __restrict__ x,
                                          __nv_bfloat16* __restrict__ hi,
                                          __nv_bfloat16* __restrict__ lo, int i) {
    float4 v = *(const float4*)(x + (size_t)i * 4);
    __nv_bfloat16 h0 = __float2bfloat16(v.x), h1 = __float2bfloat16(v.y);
    __nv_bfloat16 h2 = __float2bfloat16(v.z), h3 = __float2bfloat16(v.w);
    *(__nv_bfloat162*)(hi + (size_t)i * 4)     = __halves2bfloat162(h0, h1);
    *(__nv_bfloat162*)(hi + (size_t)i * 4 + 2) = __halves2bfloat162(h2, h3);
    *(__nv_bfloat162*)(lo + (size_t)i * 4)     = __halves2bfloat162(
        __float2bfloat16(v.x - __bfloat162float(h0)), __float2bfloat16(v.y - __bfloat162float(h1)));
    *(__nv_bfloat162*)(lo + (size_t)i * 4 + 2) = __halves2bfloat162(
        __float2bfloat16(v.z - __bfloat162float(h2)), __float2bfloat16(v.w - __bfloat162float(h3)));
}

__global__ void split_x3(const float* __restrict__ xq, const float* __restrict__ xk,
                         const float* __restrict__ xv, int n4) {
    int i = blockIdx.x * blockDim.x + threadIdx.x;
    if (i >= n4) return;
    if (blockIdx.z == 0)      split_one(xq, g_xq_h, g_xq_l, i);
    else if (blockIdx.z == 1) split_one(xk, g_xk_h, g_xk_l, i);
    else                      split_one(xv, g_xv_h, g_xv_l, i);
}
__global__ void split_w4(const float* __restrict__ wq, const float* __restrict__ wk,
                         const float* __restrict__ wv, const float* __restrict__ wo, int n4) {
    int i = blockIdx.x * blockDim.x + threadIdx.x;
    if (i >= n4) return;
    if (blockIdx.z == 0)      split_one(wq, g_wq_h, g_wq_l, i);
    else if (blockIdx.z == 1) split_one(wk, g_wk_h, g_wk_l, i);
    else if (blockIdx.z == 2) split_one(wv, g_wv_h, g_wv_l, i);
    else                      split_one(wo, g_wo_h, g_wo_l, i);
}

// ============================================================================
// shared GEMM mainloop: c[2][4][4] += X . W^T, 3-term split (unchanged)
// ============================================================================
__device__ __forceinline__ void gemm_mainloop(
    const __nv_bfloat16* __restrict__ Xh, const __nv_bfloat16* __restrict__ Xl,
    const __nv_bfloat16* __restrict__ Wh, const __nv_bfloat16* __restrict__ Wl,
    int m0, int n0, uint32_t s0, int tid, int lane, int wm, int wn,
    float c[2][4][4]) {
    auto issue = [&](int ch, int buf) {
        const size_t xb = (size_t)m0 * CC + ch * 64;
        const size_t wb = (size_t)n0 * CC + ch * 64;
        const uint32_t base = s0 + buf * 4 * TILEB;
        #pragma unroll
        for (int t = 0; t < 2; t++) {
            const int id = tid + NT * t, row = id >> 3, seg = id & 7;
            const uint32_t doff = (uint32_t)(row * LDT + seg * 8) * 2;
            const size_t sx = xb + (size_t)row * CC + seg * 8;
            const size_t sw = wb + (size_t)row * CC + seg * 8;
            CPA16(base + 0 * TILEB + doff, Xh + sx);
            CPA16(base + 1 * TILEB + doff, Xl + sx);
            CPA16(base + 2 * TILEB + doff, Wh + sw);
            CPA16(base + 3 * TILEB + doff, Wl + sw);
        }
    };
    issue(0, 0); CPA_COMMIT(); CPA_WAIT(0);
    __syncthreads();
    int buf = 0;
    for (int ch = 0; ch < 12; ch++) {
        if (ch < 11) { issue(ch + 1, buf ^ 1); CPA_COMMIT(); }
        const uint32_t aH = s0 + buf * 4 * TILEB, aL = aH + TILEB;
        const uint32_t bH = aL + TILEB, bL = bH + TILEB;
        #pragma unroll
        for (int ks = 0; ks < 4; ks++) {
            uint32_t ah[2][4], al[2][4], bh[4][2], bl[4][2];
            #pragma unroll
            for (int mi = 0; mi < 2; mi++) {
                uint32_t off = ((wm * 32 + mi * 16 + (lane & 15)) * LDT + ks * 16 + (lane >> 4) * 8) * 2;
                ldsm_x4(ah[mi], aH + off);
                ldsm_x4(al[mi], aL + off);
            }
            #pragma unroll
            for (int ni = 0; ni < 4; ni++) {
                uint32_t off = ((wn * 32 + ni * 8 + (lane & 7)) * LDT + ks * 16 + ((lane >> 3) & 1) * 8) * 2;
                ldsm_x2(bh[ni], bH + off);
                ldsm_x2(bl[ni], bL + off);
            }
            #pragma unroll
            for (int mi = 0; mi < 2; mi++)
                #pragma unroll
                for (int ni = 0; ni < 4; ni++) {
                    mma_bf16(c[mi][ni], ah[mi], bh[ni]);
                    mma_bf16(c[mi][ni], ah[mi], bl[ni]);
                    mma_bf16(c[mi][ni], al[mi], bh[ni]);
                }
        }
        CPA_WAIT(0);
        __syncthreads();
        buf ^= 1;
    }
}

// QKV projections merged: grid.z selects tensor; head-major pre-split output
__global__ void __launch_bounds__(NT, 1) tc_gemm_qkv() {
    extern __shared__ char sm[];
    const uint32_t s0 = smem_u32(sm);
    const int tid = threadIdx.x, lane = tid & 31, wid = tid >> 5;
    const int wm = wid & 3, wn = wid >> 2;
    const int m0 = blockIdx.y * 128, n0 = blockIdx.x * 128, z = blockIdx.z;
    const __nv_bfloat16 *Xh, *Xl, *Wh, *Wl;
    __nv_bfloat16 *Yh, *Yl;
    if (z == 0)      { Xh = g_xq_h; Xl = g_xq_l; Wh = g_wq_h; Wl = g_wq_l; Yh = g_Qh; Yl = g_Ql; }
    else if (z == 1) { Xh = g_xk_h; Xl = g_xk_l; Wh = g_wk_h; Wl = g_wk_l; Yh = g_Kh; Yl = g_Kl; }
    else             { Xh = g_xv_h; Xl = g_xv_l; Wh = g_wv_h; Wl = g_wv_l; Yh = g_Vh; Yl = g_Vl; }

    float c[2][4][4] = {};
    gemm_mainloop(Xh, Xl, Wh, Wl, m0, n0, s0, tid, lane, wm, wn, c);

    const int qr = lane >> 2, qc = (lane & 3) * 2;
    #pragma unroll
    for (int mi = 0; mi < 2; mi++)
        #pragma unroll
        for (int ni = 0; ni < 4; ni++) {
            const int rowg = m0 + wm * 32 + mi * 16 + qr;
            const int b = rowg >> 10, r = rowg & 1023;
            const int col = n0 + wn * 32 + ni * 8 + qc;
            const int h = col >> 6, d = col & 63;
            const size_t o0 = ((size_t)(b * HH + h) * NN + r) * DD + d;
            const size_t o1 = o0 + (size_t)8 * DD;
            float x0 = c[mi][ni][0], x1 = c[mi][ni][1];
            float x2 = c[mi][ni][2], x3 = c[mi][ni][3];
            *(uint32_t*)(Yh + o0) = packbf(x0, x1);
            *(uint32_t*)(Yh + o1) = packbf(x2, x3);
            *(uint32_t*)(Yl + o0) = packbf(bflo(x0), bflo(x1));
            *(uint32_t*)(Yl + o1) = packbf(bflo(x2), bflo(x3));
        }
}

// output projection: AO @ Wo + bo -> fp32
__global__ void __launch_bounds__(NT, 1) tc_gemm_out(const float* __restrict__ bias,
                                                     float* __restrict__ Yf) {
    extern __shared__ char sm[];
    const uint32_t s0 = smem_u32(sm);
    const int tid = threadIdx.x, lane = tid & 31, wid = tid >> 5;
    const int wm = wid & 3, wn = wid >> 2;
    const int m0 = blockIdx.y * 128, n0 = blockIdx.x * 128;

    float c[2][4][4] = {};
    gemm_mainloop(g_AOh, g_AOl, g_wo_h, g_wo_l, m0, n0, s0, tid, lane, wm, wn, c);

    const int qr = lane >> 2, qc = (lane & 3) * 2;
    #pragma unroll
    for (int mi = 0; mi < 2; mi++)
        #pragma unroll
        for (int ni = 0; ni < 4; ni++) {
            const int row = m0 + wm * 32 + mi * 16 + qr;
            const int col = n0 + wn * 32 + ni * 8 + qc;
            *(float2*)(Yf + (size_t)row * CC + col) =
                make_float2(c[mi][ni][0] + bias[col], c[mi][ni][1] + bias[col + 1]);
            *(float2*)(Yf + (size_t)(row + 8) * CC + col) =
                make_float2(c[mi][ni][2] + bias[col], c[mi][ni][3] + bias[col + 1]);
        }
}

// copy a head-major 128x64 bf16 tile pair (hi,lo) to smem, 512 threads
__device__ __forceinline__ void cpa_tile_pair(uint32_t dhi, uint32_t dlo,
                                              const __nv_bfloat16* __restrict__ shi,
                                              const __nv_bfloat16* __restrict__ slo,
                                              size_t base, int tid) {
    #pragma unroll
    for (int t = 0; t < 2; t++) {
        const int id = tid + NT * t, row = id >> 3, seg = id & 7;
        const uint32_t doff = (uint32_t)(row * LDT + seg * 8) * 2;
        const size_t s = base + (size_t)row * 64 + seg * 8;
        CPA16(dhi + doff, shi + s);
        CPA16(dlo + doff, slo + s);
    }
}
// 256-thread variants: 64-row and 128-row tiles
__device__ __forceinline__ void cpa_q64_256(uint32_t dhi, uint32_t dlo,
                                            const __nv_bfloat16* __restrict__ shi,
                                            const __nv_bfloat16* __restrict__ slo,
                                            size_t base, int tid) {
    #pragma unroll
    for (int t = 0; t < 2; t++) {
        const int id = tid + 256 * t, row = id >> 3, seg = id & 7;
        const uint32_t doff = (uint32_t)(row * LDT + seg * 8) * 2;
        const size_t s = base + (size_t)row * 64 + seg * 8;
        CPA16(dhi + doff, shi + s);
        CPA16(dlo + doff, slo + s);
    }
}
__device__ __forceinline__ void cpa_k128_256(uint32_t dhi, uint32_t dlo,
                                             const __nv_bfloat16* __restrict__ shi,
                                             const __nv_bfloat16* __restrict__ slo,
                                             size_t base, int tid) {
    #pragma unroll
    for (int t = 0; t < 4; t++) {
        const int id = tid + 256 * t, row = id >> 3, seg = id & 7;
        const uint32_t doff = (uint32_t)(row * LDT + seg * 8) * 2;
        const size_t s = base + (size_t)row * 64 + seg * 8;
        CPA16(dhi + doff, shi + s);
        CPA16(dlo + doff, slo + s);
    }
}

// ============================================================================
// Pass 1: 256-thread CTA over 64 q-rows -> 2 CTAs/SM (phase overlap).
// smem: Q(2x9216) + K dbuf(4x18432) + red(2048) = 94208 B.
// ============================================================================
__global__ void __launch_bounds__(256, 2) attn_stats(const float* __restrict__ AW) {
    extern __shared__ char sm[];
    const uint32_t s0 = smem_u32(sm);
    const uint32_t sQH = s0, sQL = s0 + QTILEB;
    const uint32_t kBase = s0 + 2 * QTILEB;
    float* redS = (float*)(sm + 2 * QTILEB + 4 * TILEB);
    float* redU = redS + 4 * 64;

    const int tid = threadIdx.x, lane = tid & 31, wid = tid >> 5;
    const int wm = wid & 1, wn = wid >> 1;
    const int bh = blockIdx.y;
    const int q0 = blockIdx.x * 64;
    const int qr = lane >> 2, qc = (lane & 3) * 2;

    const size_t qbase = ((size_t)bh * NN + q0) * DD;
    const size_t kbase0 = (size_t)bh * SS * DD;

    cpa_q64_256(sQH, sQL, g_Qh, g_Ql, qbase, tid);
    cpa_k128_256(kBase, kBase + TILEB, g_Kh, g_Kl, kbase0, tid);
    CPA_COMMIT(); CPA_WAIT(0);
    __syncthreads();

    float ssum[4] = {}, usum[4] = {};

    for (int sc = 0; sc < 8; sc++) {
        const int buf = sc & 1;
        if (sc < 7) {
            const uint32_t kb = kBase + (buf ^ 1) * 2 * TILEB;
            cpa_k128_256(kb, kb + TILEB, g_Kh, g_Kl, kbase0 + (size_t)(sc + 1) * 128 * DD, tid);
            CPA_COMMIT();
        }
        const uint32_t kH = kBase + buf * 2 * TILEB, kL = kH + TILEB;

        float c[2][4][4] = {};
        #pragma unroll
        for (int ks = 0; ks < 4; ks++) {
            uint32_t ah[2][4], al[2][4], bh2[4][2], bl2[4][2];
            #pragma unroll
            for (int mi = 0; mi < 2; mi++) {
                uint32_t off = ((wm * 32 + mi * 16 + (lane & 15)) * LDT + ks * 16 + (lane >> 4) * 8) * 2;
                ldsm_x4(ah[mi], sQH + off);
                ldsm_x4(al[mi], sQL + off);
            }
            #pragma unroll
            for (int ni = 0; ni < 4; ni++) {
                uint32_t off = ((wn * 32 + ni * 8 + (lane & 7)) * LDT + ks * 16 + ((lane >> 3) & 1) * 8) * 2;
                ldsm_x2(bh2[ni], kH + off);
                ldsm_x2(bl2[ni], kL + off);
            }
            #pragma unroll
            for (int mi = 0; mi < 2; mi++)
                #pragma unroll
                for (int ni = 0; ni < 4; ni++) {
                    mma_bf16(c[mi][ni], ah[mi], bh2[ni]);
                    mma_bf16(c[mi][ni], ah[mi], bl2[ni]);
                    mma_bf16(c[mi][ni], al[mi], bh2[ni]);
                }
        }

        const int s0c = sc * 128;
        #pragma unroll
        for (int mi = 0; mi < 2; mi++) {
            const size_t rb = ((size_t)bh * NN + q0 + wm * 32 + mi * 16 + qr) * SS + s0c + wn * 32 + qc;
            #pragma unroll
            for (int ni = 0; ni < 4; ni++) {
                float2 aw0 = *(const float2*)(AW + rb + ni * 8);
                float2 aw1 = *(const float2*)(AW + rb + (size_t)8 * SS + ni * 8);
                float sc00 = c[mi][ni][0] * SCALEF, sc01 = c[mi][ni][1] * SCALEF;
                float sc10 = c[mi][ni][2] * SCALEF, sc11 = c[mi][ni][3] * SCALEF;
                ssum[mi * 2]     += __expf(sc00) + __expf(sc01);
                ssum[mi * 2 + 1] += __expf(sc10) + __expf(sc11);
                usum[mi * 2]     += __expf(sc00 + aw0.x) + __expf(sc01 + aw0.y);
                usum[mi * 2 + 1] += __expf(sc10 + aw1.x) + __expf(sc11 + aw1.y);
            }
        }
        CPA_WAIT(0);
        __syncthreads();
    }

    #pragma unroll
    for (int sl = 0; sl < 4; sl++) {
        ssum[sl] += __shfl_xor_sync(~0u, ssum[sl], 1);
        ssum[sl] += __shfl_xor_sync(~0u, ssum[sl], 2);
        usum[sl] += __shfl_xor_sync(~0u, usum[sl], 1);
        usum[sl] += __shfl_xor_sync(~0u, usum[sl], 2);
    }
    if ((lane & 3) == 0) {
        #pragma unroll
        for (int sl = 0; sl < 4; sl++) {
            const int row = wm * 32 + (sl >> 1) * 16 + qr + 8 * (sl & 1);
            redS[wn * 64 + row] = ssum[sl];
            redU[wn * 64 + row] = usum[sl];
        }
    }
    __syncthreads();
    if (tid < 64) {
        float st = redS[tid] + redS[64 + tid] + redS[128 + tid] + redS[192 + tid];
        float ut = redU[tid] + redU[64 + tid] + redU[128 + tid] + redU[192 + tid];
        const int gi = bh * NN + q0 + tid;
        g_lse[gi] = __logf(st);
        g_isu[gi] = 1.0f / ut;
    }
}

// ============================================================================
// Pass 2 (R9-verbatim): logits + p, O = Phi.Vhi + Phi.Vlo + Plo.Vhi via smem P.
// ============================================================================
__global__ void __launch_bounds__(NT, 1) attn_av(const float* __restrict__ AW,
                                                 float* __restrict__ LOGOUT) {
    extern __shared__ char sm[];
    const uint32_t s0 = smem_u32(sm);
    const uint32_t sQH = s0, sQL = s0 + TILEB;
    const uint32_t sVH = s0 + 6 * TILEB, sVL = s0 + 7 * TILEB;
    const uint32_t pH = s0 + 8 * TILEB, pL = pH + PTILEB;

    const int tid = threadIdx.x, lane = tid & 31, wid = tid >> 5;
    const int wm = wid & 3, wn = wid >> 2;
    const int bh = blockIdx.y;
    const int q0 = blockIdx.x * 128;
    const int qr = lane >> 2, qc = (lane & 3) * 2;

    const size_t qbase = ((size_t)bh * NN + q0) * DD;
    const size_t kvbase = (size_t)bh * SS * DD;

    cpa_tile_pair(sQH, sQL, g_Qh, g_Ql, qbase, tid);
    cpa_tile_pair(s0 + 2 * TILEB, s0 + 3 * TILEB, g_Kh, g_Kl, kvbase, tid);
    CPA_COMMIT(); CPA_WAIT(0);
    __syncthreads();

    float lse_r[4], isu_r[4];
    #pragma unroll
    for (int sl = 0; sl < 4; sl++) {
        const int row = q0 + wm * 32 + (sl >> 1) * 16 + qr + 8 * (sl & 1);
        lse_r[sl] = g_lse[bh * NN + row];
        isu_r[sl] = g_isu[bh * NN + row];
    }

    float c2[2][2][4] = {};
    int buf = 0;

    for (int sc = 0; sc < 8; sc++) {
        cpa_tile_pair(sVH, sVL, g_Vh, g_Vl, kvbase + (size_t)sc * 128 * DD, tid);
        CPA_COMMIT();
        if (sc < 7) {
            cpa_tile_pair(s0 + (2 + 2 * (buf ^ 1)) * TILEB, s0 + (3 + 2 * (buf ^ 1)) * TILEB,
                          g_Kh, g_Kl, kvbase + (size_t)(sc + 1) * 128 * DD, tid);
            CPA_COMMIT();
        }
        const uint32_t kH = s0 + (2 + 2 * buf) * TILEB, kL = kH + TILEB;

        float c[2][4][4] = {};
        #pragma unroll
        for (int ks = 0; ks < 4; ks++) {
            uint32_t ah[2][4], al[2][4], bh2[4][2], bl2[4][2];
            #pragma unroll
            for (int mi = 0; mi < 2; mi++) {
                uint32_t off = ((wm * 32 + mi * 16 + (lane & 15)) * LDT + ks * 16 + (lane >> 4) * 8) * 2;
                ldsm_x4(ah[mi], sQH + off);
                ldsm_x4(al[mi], sQL + off);
            }
            #pragma unroll
            for (int ni = 0; ni < 4; ni++) {
                uint32_t off = ((wn * 32 + ni * 8 + (lane & 7)) * LDT + ks * 16 + ((lane >> 3) & 1) * 8) * 2;
                ldsm_x2(bh2[ni], kH + off);
                ldsm_x2(bl2[ni], kL + off);
            }
            #pragma unroll
            for (int mi = 0; mi < 2; mi++)
                #pragma unroll
                for (int ni = 0; ni < 4; ni++) {
                    mma_bf16(c[mi][ni], ah[mi], bh2[ni]);
                    mma_bf16(c[mi][ni], ah[mi], bl2[ni]);
                    mma_bf16(c[mi][ni], al[mi], bh2[ni]);
                }
        }

        const int s0c = sc * 128;
        #pragma unroll
        for (int mi = 0; mi < 2; mi++) {
            const size_t rb = ((size_t)bh * NN + q0 + wm * 32 + mi * 16 + qr) * SS + s0c + wn * 32 + qc;
            const int prow0 = wm * 32 + mi * 16 + qr;
            #pragma unroll
            for (int ni = 0; ni < 4; ni++) {
                float2 aw0 = *(const float2*)(AW + rb + ni * 8);
                float2 aw1 = *(const float2*)(AW + rb + (size_t)8 * SS + ni * 8);
                float u00 = fmaf(c[mi][ni][0], SCALEF, aw0.x);
                float u01 = fmaf(c[mi][ni][1], SCALEF, aw0.y);
                float u10 = fmaf(c[mi][ni][2], SCALEF, aw1.x);
                float u11 = fmaf(c[mi][ni][3], SCALEF, aw1.y);
                const int sl0 = mi * 2, sl1 = mi * 2 + 1;
                *(float2*)(LOGOUT + rb + ni * 8) = make_float2(u00 - lse_r[sl0], u01 - lse_r[sl0]);
                *(float2*)(LOGOUT + rb + (size_t)8 * SS + ni * 8) = make_float2(u10 - lse_r[sl1], u11 - lse_r[sl1]);
                float p00 = __expf(u00) * isu_r[sl0], p01 = __expf(u01) * isu_r[sl0];
                float p10 = __expf(u10) * isu_r[sl1], p11 = __expf(u11) * isu_r[sl1];
                const int pcol = wn * 32 + ni * 8 + qc;
                *(uint32_t*)(sm + (pH - s0) + (prow0 * LDP + pcol) * 2)       = packbf(p00, p01);
                *(uint32_t*)(sm + (pH - s0) + ((prow0 + 8) * LDP + pcol) * 2) = packbf(p10, p11);
                *(uint32_t*)(sm + (pL - s0) + (prow0 * LDP + pcol) * 2)       = packbf(bflo(p00), bflo(p01));
                *(uint32_t*)(sm + (pL - s0) + ((prow0 + 8) * LDP + pcol) * 2) = packbf(bflo(p10), bflo(p11));
            }
        }
        if (sc < 7) { CPA_WAIT(1); } else { CPA_WAIT(0); }
        __syncthreads();

        #pragma unroll
        for (int ksp = 0; ksp < 8; ksp++) {
            uint32_t pa[2][4], pe[2][4], vh[2][2], vl[2][2];
            #pragma unroll
            for (int mi = 0; mi < 2; mi++) {
                uint32_t off = ((wm * 32 + mi * 16 + (lane & 15)) * LDP + ksp * 16 + (lane >> 4) * 8) * 2;
                ldsm_x4(pa[mi], pH + off);
                ldsm_x4(pe[mi], pL + off);
            }
            #pragma unroll
            for (int nj = 0; nj < 2; nj++) {
                uint32_t off = ((ksp * 16 + (lane & 15)) * LDT + wn * 16 + nj * 8) * 2;
                ldsm_x2t(vh[nj], sVH + off);
                ldsm_x2t(vl[nj], sVL + off);
            }
            #pragma unroll
            for (int mi = 0; mi < 2; mi++)
                #pragma unroll
                for (int nj = 0; nj < 2; nj++) {
                    mma_bf16(c2[mi][nj], pa[mi], vh[nj]);
                    mma_bf16(c2[mi][nj], pa[mi], vl[nj]);
                    mma_bf16(c2[mi][nj], pe[mi], vh[nj]);
                }
        }
        CPA_WAIT(0);
        __syncthreads();
        buf ^= 1;
    }

    const int b = bh / HH, h = bh % HH;
    #pragma unroll
    for (int mi = 0; mi < 2; mi++)
        #pragma unroll
        for (int nj = 0; nj < 2; nj++) {
            const int row = q0 + wm * 32 + mi * 16 + qr;
            const int col = h * DD + wn * 16 + nj * 8 + qc;
            const size_t o0 = (size_t)(b * NN + row) * CC + col;
            const size_t o1 = (size_t)(b * NN + row + 8) * CC + col;
            float x0 = c2[mi][nj][0], x1 = c2[mi][nj][1];
            float x2 = c2[mi][nj][2], x3 = c2[mi][nj][3];
            *(uint32_t*)(g_AOh + o0) = packbf(x0, x1);
            *(uint32_t*)(g_AOh + o1) = packbf(x2, x3);
            *(uint32_t*)(g_AOl + o0) = packbf(bflo(x0), bflo(x1));
            *(uint32_t*)(g_AOl + o1) = packbf(bflo(x2), bflo(x3));
        }
}

// ============================================================================
extern "C" void kernel_launch(void* const* d_in, const int* in_sizes, int n_in,
                              void* d_out, int out_size) {
    const float* query = (const float*)d_in[0];
    const float* key_  = (const float*)d_in[1];
    const float* value = (const float*)d_in[2];
    const float* aw    = (const float*)d_in[3];
    const float* Wq    = (const float*)d_in[4];
    const float* Wk    = (const float*)d_in[5];
    const float* Wv    = (const float*)d_in[6];
    const float* Wo    = (const float*)d_in[7];
    const float* bo    = (const float*)d_in[8];

    float* out    = (float*)d_out;                       // [B,N,C]
    float* logout = out + (size_t)BB * NN * CC;          // [B,H,N,S]

    const int smem_gemm  = 8 * TILEB;                    // 147456
    const int smem_stats = 2 * QTILEB + 4 * TILEB + 2048; // 94208
    const int smem_av    = 8 * TILEB + 2 * PTILEB;       // 217088
    cudaFuncSetAttribute(tc_gemm_qkv, cudaFuncAttributeMaxDynamicSharedMemorySize, smem_gemm);
    cudaFuncSetAttribute(tc_gemm_out, cudaFuncAttributeMaxDynamicSharedMemorySize, smem_gemm);
    cudaFuncSetAttribute(attn_stats,  cudaFuncAttributeMaxDynamicSharedMemorySize, smem_stats);
    cudaFuncSetAttribute(attn_av,     cudaFuncAttributeMaxDynamicSharedMemorySize, smem_av);

    const int nX4 = (BB * NN * CC) / 4;
    const int nW4 = (CC * CC) / 4;
    dim3 gsx((nX4 + 255) / 256, 1, 3);
    dim3 gsw((nW4 + 255) / 256, 1, 4);
    dim3 gqkv(CC / 128, (BB * NN) / 128, 3);   // 6 x 64 x 3
    dim3 gp(CC / 128, (BB * NN) / 128);        // 6 x 64
    dim3 gst(NN / 64, BB * HH);                // 16 x 96
    dim3 ga(NN / 128, BB * HH);                // 8 x 96

    split_x3<<<gsx, 256>>>(query, key_, value, nX4);
    split_w4<<<gsw, 256>>>(Wq, Wk, Wv, Wo, nW4);
    tc_gemm_qkv<<<gqkv, NT, smem_gemm>>>();
    attn_stats<<<gst, 256, smem_stats>>>(aw);
    attn_av<<<ga, NT, smem_av>>>(aw, logout);
    tc_gemm_out<<<gp, NT, smem_gemm>>>(bo, out);
}

// round 13
// speedup vs baseline: 1.1208x; 1.0584x over previous
#include <cuda_runtime.h>
#include <cuda_bf16.h>
#include <math.h>
#include <stdint.h>

#define BB 8
#define NN 1024
#define SS 1024
#define CC 768
#define HH 12
#define DD 64
#define SCALEF 0.125f

#define LDT 72        // bf16 elems per 64-wide tile row (144B, conflict-free)
#define TILEB (128 * LDT * 2)   // 18432 B per 128x64 bf16 tile
#define QTILEB (64 * LDT * 2)   // 9216 B per 64x64 bf16 tile
#define ATILE 18432
#define BTILE 9216
#define GBUF (2 * ATILE + 2 * BTILE)   // 55296 per gemm buffer

// -------- scratch (device globals; no allocation allowed) --------
__device__ __align__(256) __nv_bfloat16 g_xq_h[(size_t)BB * NN * CC];
__device__ __align__(256) __nv_bfloat16 g_xq_l[(size_t)BB * NN * CC];
__device__ __align__(256) __nv_bfloat16 g_xk_h[(size_t)BB * SS * CC];
__device__ __align__(256) __nv_bfloat16 g_xk_l[(size_t)BB * SS * CC];
__device__ __align__(256) __nv_bfloat16 g_xv_h[(size_t)BB * SS * CC];
__device__ __align__(256) __nv_bfloat16 g_xv_l[(size_t)BB * SS * CC];
__device__ __align__(256) __nv_bfloat16 g_wq_h[(size_t)CC * CC];
__device__ __align__(256) __nv_bfloat16 g_wq_l[(size_t)CC * CC];
__device__ __align__(256) __nv_bfloat16 g_wk_h[(size_t)CC * CC];
__device__ __align__(256) __nv_bfloat16 g_wk_l[(size_t)CC * CC];
__device__ __align__(256) __nv_bfloat16 g_wv_h[(size_t)CC * CC];
__device__ __align__(256) __nv_bfloat16 g_wv_l[(size_t)CC * CC];
__device__ __align__(256) __nv_bfloat16 g_wo_h[(size_t)CC * CC];
__device__ __align__(256) __nv_bfloat16 g_wo_l[(size_t)CC * CC];
__device__ __align__(256) __nv_bfloat16 g_Qh[(size_t)BB * HH * NN * DD];
__device__ __align__(256) __nv_bfloat16 g_Ql[(size_t)BB * HH * NN * DD];
__device__ __align__(256) __nv_bfloat16 g_Kh[(size_t)BB * HH * SS * DD];
__device__ __align__(256) __nv_bfloat16 g_Kl[(size_t)BB * HH * SS * DD];
__device__ __align__(256) __nv_bfloat16 g_Vh[(size_t)BB * HH * SS * DD];
__device__ __align__(256) __nv_bfloat16 g_Vl[(size_t)BB * HH * SS * DD];
__device__ __align__(256) __nv_bfloat16 g_AOh[(size_t)BB * NN * CC];
__device__ __align__(256) __nv_bfloat16 g_AOl[(size_t)BB * NN * CC];
__device__ float g_lse[BB * HH * NN];
__device__ float g_isu[BB * HH * NN];

// ============================================================================
// helpers
// ============================================================================
__device__ __forceinline__ uint32_t smem_u32(const void* p) {
    uint32_t a;
    asm("{ .reg .u64 t; cvta.to.shared.u64 t, %1; cvt.u32.u64 %0, t; }" : "=r"(a) : "l"(p));
    return a;
}
__device__ __forceinline__ void mma_bf16(float* c, const uint32_t* a, const uint32_t* b) {
    asm volatile("mma.sync.aligned.m16n8k16.row.col.f32.bf16.bf16.f32 "
        "{%0,%1,%2,%3}, {%4,%5,%6,%7}, {%8,%9}, {%0,%1,%2,%3};"
        : "+f"(c[0]), "+f"(c[1]), "+f"(c[2]), "+f"(c[3])
        : "r"(a[0]), "r"(a[1]), "r"(a[2]), "r"(a[3]), "r"(b[0]), "r"(b[1]));
}
__device__ __forceinline__ void ldsm_x4(uint32_t* r, uint32_t a) {
    asm volatile("ldmatrix.sync.aligned.m8n8.x4.shared.b16 {%0,%1,%2,%3}, [%4];"
        : "=r"(r[0]), "=r"(r[1]), "=r"(r[2]), "=r"(r[3]) : "r"(a));
}
__device__ __forceinline__ void ldsm_x2(uint32_t* r, uint32_t a) {
    asm volatile("ldmatrix.sync.aligned.m8n8.x2.shared.b16 {%0,%1}, [%2];"
        : "=r"(r[0]), "=r"(r[1]) : "r"(a));
}
__device__ __forceinline__ void ldsm_x2t(uint32_t* r, uint32_t a) {
    asm volatile("ldmatrix.sync.aligned.m8n8.x2.trans.shared.b16 {%0,%1}, [%2];"
        : "=r"(r[0]), "=r"(r[1]) : "r"(a));
}
#define CPA16(dst, src) \
    asm volatile("cp.async.cg.shared.global [%0], [%1], 16;" :: "r"(dst), "l"(src) : "memory")
#define CPA_COMMIT() asm volatile("cp.async.commit_group;" ::: "memory")
#define CPA_WAIT(n)  asm volatile("cp.async.wait_group %0;" :: "n"(n) : "memory")

__device__ __forceinline__ uint32_t packbf(float x, float y) {
    __nv_bfloat162 t = __halves2bfloat162(__float2bfloat16(x), __float2bfloat16(y));
    return *(uint32_t*)&t;
}
__device__ __forceinline__ float bflo(float x) {
    return x - __bfloat162float(__float2bfloat16(x));
}

// ============================================================================
// fp32 -> bf16 hi/lo split; z selects among up to 4 tensors
// ============================================================================
__device__ __forceinline__ void split_one(const float* __restrict__ x,
                                          __nv_bfloat16* __restrict__ hi,
                                          __nv_bfloat16* __restrict__ lo, int i) {
    float4 v = *(const float4*)(x + (size_t)i * 4);
    __nv_bfloat16 h0 = __float2bfloat16(v.x), h1 = __float2bfloat16(v.y);
    __nv_bfloat16 h2 = __float2bfloat16(v.z), h3 = __float2bfloat16(v.w);
    *(__nv_bfloat162*)(hi + (size_t)i * 4)     = __halves2bfloat162(h0, h1);
    *(__nv_bfloat162*)(hi + (size_t)i * 4 + 2) = __halves2bfloat162(h2, h3);
    *(__nv_bfloat162*)(lo + (size_t)i * 4)     = __halves2bfloat162(
        __float2bfloat16(v.x - __bfloat162float(h0)), __float2bfloat16(v.y - __bfloat162float(h1)));
    *(__nv_bfloat162*)(lo + (size_t)i * 4 + 2) = __halves2bfloat162(
        __float2bfloat16(v.z - __bfloat162float(h2)), __float2bfloat16(v.w - __bfloat162float(h3)));
}

__global__ void split_x3(const float* __restrict__ xq, const float* __restrict__ xk,
                         const float* __restrict__ xv, int n4) {
    int i = blockIdx.x * blockDim.x + threadIdx.x;
    if (i >= n4) return;
    if (blockIdx.z == 0)      split_one(xq, g_xq_h, g_xq_l, i);
    else if (blockIdx.z == 1) split_one(xk, g_xk_h, g_xk_l, i);
    else                      split_one(xv, g_xv_h, g_xv_l, i);
}
__global__ void split_w4(const float* __restrict__ wq, const float* __restrict__ wk,
                         const float* __restrict__ wv, const float* __restrict__ wo, int n4) {
    int i = blockIdx.x * blockDim.x + threadIdx.x;
    if (i >= n4) return;
    if (blockIdx.z == 0)      split_one(wq, g_wq_h, g_wq_l, i);
    else if (blockIdx.z == 1) split_one(wk, g_wk_h, g_wk_l, i);
    else if (blockIdx.z == 2) split_one(wv, g_wv_h, g_wv_l, i);
    else                      split_one(wo, g_wo_h, g_wo_l, i);
}

// ============================================================================
// GEMM mainloop, 256 threads, 128x64 output tile, double-buffered cp.async.
// c[2][4][4] += X[128 x CC] . W[64 x CC]^T, 3-term split.
// warp grid 4(m) x 2(n), warp tile 32x32.
// ============================================================================
__device__ __forceinline__ void gemm_mainloop256(
    const __nv_bfloat16* __restrict__ Xh, const __nv_bfloat16* __restrict__ Xl,
    const __nv_bfloat16* __restrict__ Wh, const __nv_bfloat16* __restrict__ Wl,
    int m0, int n0, uint32_t s0, int tid, int lane, int wm, int wn,
    float c[2][4][4]) {
    auto issue = [&](int ch, int buf) {
        const uint32_t base = s0 + buf * GBUF;
        #pragma unroll
        for (int t = 0; t < 4; t++) {
            const int id = tid + 256 * t, row = id >> 3, seg = id & 7;
            const uint32_t doff = (uint32_t)(row * LDT + seg * 8) * 2;
            const size_t sx = (size_t)(m0 + row) * CC + ch * 64 + seg * 8;
            CPA16(base + doff, Xh + sx);
            CPA16(base + ATILE + doff, Xl + sx);
        }
        #pragma unroll
        for (int t = 0; t < 2; t++) {
            const int id = tid + 256 * t, row = id >> 3, seg = id & 7;
            const uint32_t doff = (uint32_t)(row * LDT + seg * 8) * 2;
            const size_t sw = (size_t)(n0 + row) * CC + ch * 64 + seg * 8;
            CPA16(base + 2 * ATILE + doff, Wh + sw);
            CPA16(base + 2 * ATILE + BTILE + doff, Wl + sw);
        }
    };
    issue(0, 0); CPA_COMMIT(); CPA_WAIT(0);
    __syncthreads();
    int buf = 0;
    for (int ch = 0; ch < 12; ch++) {
        if (ch < 11) { issue(ch + 1, buf ^ 1); CPA_COMMIT(); }
        const uint32_t aH = s0 + buf * GBUF, aL = aH + ATILE;
        const uint32_t bH = aL + ATILE, bL = bH + BTILE;
        #pragma unroll
        for (int ks = 0; ks < 4; ks++) {
            uint32_t ah[2][4], al[2][4], bh[4][2], bl[4][2];
            #pragma unroll
            for (int mi = 0; mi < 2; mi++) {
                uint32_t off = ((wm * 32 + mi * 16 + (lane & 15)) * LDT + ks * 16 + (lane >> 4) * 8) * 2;
                ldsm_x4(ah[mi], aH + off);
                ldsm_x4(al[mi], aL + off);
            }
            #pragma unroll
            for (int ni = 0; ni < 4; ni++) {
                uint32_t off = ((wn * 32 + ni * 8 + (lane & 7)) * LDT + ks * 16 + ((lane >> 3) & 1) * 8) * 2;
                ldsm_x2(bh[ni], bH + off);
                ldsm_x2(bl[ni], bL + off);
            }
            #pragma unroll
            for (int mi = 0; mi < 2; mi++)
                #pragma unroll
                for (int ni = 0; ni < 4; ni++) {
                    mma_bf16(c[mi][ni], ah[mi], bh[ni]);
                    mma_bf16(c[mi][ni], ah[mi], bl[ni]);
                    mma_bf16(c[mi][ni], al[mi], bh[ni]);
                }
        }
        CPA_WAIT(0);
        __syncthreads();
        buf ^= 1;
    }
}

// QKV projections merged: grid.z selects tensor; head-major pre-split output
__global__ void __launch_bounds__(256, 2) tc_gemm_qkv() {
    extern __shared__ char sm[];
    const uint32_t s0 = smem_u32(sm);
    const int tid = threadIdx.x, lane = tid & 31, wid = tid >> 5;
    const int wm = wid & 3, wn = wid >> 2;
    const int m0 = blockIdx.y * 128, n0 = blockIdx.x * 64, z = blockIdx.z;
    const __nv_bfloat16 *Xh, *Xl, *Wh, *Wl;
    __nv_bfloat16 *Yh, *Yl;
    if (z == 0)      { Xh = g_xq_h; Xl = g_xq_l; Wh = g_wq_h; Wl = g_wq_l; Yh = g_Qh; Yl = g_Ql; }
    else if (z == 1) { Xh = g_xk_h; Xl = g_xk_l; Wh = g_wk_h; Wl = g_wk_l; Yh = g_Kh; Yl = g_Kl; }
    else             { Xh = g_xv_h; Xl = g_xv_l; Wh = g_wv_h; Wl = g_wv_l; Yh = g_Vh; Yl = g_Vl; }

    float c[2][4][4] = {};
    gemm_mainloop256(Xh, Xl, Wh, Wl, m0, n0, s0, tid, lane, wm, wn, c);

    const int qr = lane >> 2, qc = (lane & 3) * 2;
    #pragma unroll
    for (int mi = 0; mi < 2; mi++)
        #pragma unroll
        for (int ni = 0; ni < 4; ni++) {
            const int rowg = m0 + wm * 32 + mi * 16 + qr;
            const int b = rowg >> 10, r = rowg & 1023;
            const int col = n0 + wn * 32 + ni * 8 + qc;
            const int h = col >> 6, d = col & 63;
            const size_t o0 = ((size_t)(b * HH + h) * NN + r) * DD + d;
            const size_t o1 = o0 + (size_t)8 * DD;
            float x0 = c[mi][ni][0], x1 = c[mi][ni][1];
            float x2 = c[mi][ni][2], x3 = c[mi][ni][3];
            *(uint32_t*)(Yh + o0) = packbf(x0, x1);
            *(uint32_t*)(Yh + o1) = packbf(x2, x3);
            *(uint32_t*)(Yl + o0) = packbf(bflo(x0), bflo(x1));
            *(uint32_t*)(Yl + o1) = packbf(bflo(x2), bflo(x3));
        }
}

// output projection: AO @ Wo + bo -> fp32
__global__ void __launch_bounds__(256, 2) tc_gemm_out(const float* __restrict__ bias,
                                                      float* __restrict__ Yf) {
    extern __shared__ char sm[];
    const uint32_t s0 = smem_u32(sm);
    const int tid = threadIdx.x, lane = tid & 31, wid = tid >> 5;
    const int wm = wid & 3, wn = wid >> 2;
    const int m0 = blockIdx.y * 128, n0 = blockIdx.x * 64;

    float c[2][4][4] = {};
    gemm_mainloop256(g_AOh, g_AOl, g_wo_h, g_wo_l, m0, n0, s0, tid, lane, wm, wn, c);

    const int qr = lane >> 2, qc = (lane & 3) * 2;
    #pragma unroll
    for (int mi = 0; mi < 2; mi++)
        #pragma unroll
        for (int ni = 0; ni < 4; ni++) {
            const int row = m0 + wm * 32 + mi * 16 + qr;
            const int col = n0 + wn * 32 + ni * 8 + qc;
            *(float2*)(Yf + (size_t)row * CC + col) =
                make_float2(c[mi][ni][0] + bias[col], c[mi][ni][1] + bias[col + 1]);
            *(float2*)(Yf + (size_t)(row + 8) * CC + col) =
                make_float2(c[mi][ni][2] + bias[col], c[mi][ni][3] + bias[col + 1]);
        }
}

// 256-thread tile copies: 64-row and 128-row head-major tile pairs
__device__ __forceinline__ void cpa_t64_256(uint32_t dhi, uint32_t dlo,
                                            const __nv_bfloat16* __restrict__ shi,
                                            const __nv_bfloat16* __restrict__ slo,
                                            size_t base, int tid) {
    #pragma unroll
    for (int t = 0; t < 2; t++) {
        const int id = tid + 256 * t, row = id >> 3, seg = id & 7;
        const uint32_t doff = (uint32_t)(row * LDT + seg * 8) * 2;
        const size_t s = base + (size_t)row * 64 + seg * 8;
        CPA16(dhi + doff, shi + s);
        CPA16(dlo + doff, slo + s);
    }
}
__device__ __forceinline__ void cpa_t128_256(uint32_t dhi, uint32_t dlo,
                                             const __nv_bfloat16* __restrict__ shi,
                                             const __nv_bfloat16* __restrict__ slo,
                                             size_t base, int tid) {
    #pragma unroll
    for (int t = 0; t < 4; t++) {
        const int id = tid + 256 * t, row = id >> 3, seg = id & 7;
        const uint32_t doff = (uint32_t)(row * LDT + seg * 8) * 2;
        const size_t s = base + (size_t)row * 64 + seg * 8;
        CPA16(dhi + doff, shi + s);
        CPA16(dlo + doff, slo + s);
    }
}

// ============================================================================
// Pass 1 (R12-verbatim): 256-thread CTA over 64 q-rows, 2 CTAs/SM.
// smem: Q(2x9216) + K dbuf(4x18432) + red(2048) = 94208 B.
// ============================================================================
__global__ void __launch_bounds__(256, 2) attn_stats(const float* __restrict__ AW) {
    extern __shared__ char sm[];
    const uint32_t s0 = smem_u32(sm);
    const uint32_t sQH = s0, sQL = s0 + QTILEB;
    const uint32_t kBase = s0 + 2 * QTILEB;
    float* redS = (float*)(sm + 2 * QTILEB + 4 * TILEB);
    float* redU = redS + 4 * 64;

    const int tid = threadIdx.x, lane = tid & 31, wid = tid >> 5;
    const int wm = wid & 1, wn = wid >> 1;
    const int bh = blockIdx.y;
    const int q0 = blockIdx.x * 64;
    const int qr = lane >> 2, qc = (lane & 3) * 2;

    const size_t qbase = ((size_t)bh * NN + q0) * DD;
    const size_t kbase0 = (size_t)bh * SS * DD;

    cpa_t64_256(sQH, sQL, g_Qh, g_Ql, qbase, tid);
    cpa_t128_256(kBase, kBase + TILEB, g_Kh, g_Kl, kbase0, tid);
    CPA_COMMIT(); CPA_WAIT(0);
    __syncthreads();

    float ssum[4] = {}, usum[4] = {};

    for (int sc = 0; sc < 8; sc++) {
        const int buf = sc & 1;
        if (sc < 7) {
            const uint32_t kb = kBase + (buf ^ 1) * 2 * TILEB;
            cpa_t128_256(kb, kb + TILEB, g_Kh, g_Kl, kbase0 + (size_t)(sc + 1) * 128 * DD, tid);
            CPA_COMMIT();
        }
        const uint32_t kH = kBase + buf * 2 * TILEB, kL = kH + TILEB;

        float c[2][4][4] = {};
        #pragma unroll
        for (int ks = 0; ks < 4; ks++) {
            uint32_t ah[2][4], al[2][4], bh2[4][2], bl2[4][2];
            #pragma unroll
            for (int mi = 0; mi < 2; mi++) {
                uint32_t off = ((wm * 32 + mi * 16 + (lane & 15)) * LDT + ks * 16 + (lane >> 4) * 8) * 2;
                ldsm_x4(ah[mi], sQH + off);
                ldsm_x4(al[mi], sQL + off);
            }
            #pragma unroll
            for (int ni = 0; ni < 4; ni++) {
                uint32_t off = ((wn * 32 + ni * 8 + (lane & 7)) * LDT + ks * 16 + ((lane >> 3) & 1) * 8) * 2;
                ldsm_x2(bh2[ni], kH + off);
                ldsm_x2(bl2[ni], kL + off);
            }
            #pragma unroll
            for (int mi = 0; mi < 2; mi++)
                #pragma unroll
                for (int ni = 0; ni < 4; ni++) {
                    mma_bf16(c[mi][ni], ah[mi], bh2[ni]);
                    mma_bf16(c[mi][ni], ah[mi], bl2[ni]);
                    mma_bf16(c[mi][ni], al[mi], bh2[ni]);
                }
        }

        const int s0c = sc * 128;
        #pragma unroll
        for (int mi = 0; mi < 2; mi++) {
            const size_t rb = ((size_t)bh * NN + q0 + wm * 32 + mi * 16 + qr) * SS + s0c + wn * 32 + qc;
            #pragma unroll
            for (int ni = 0; ni < 4; ni++) {
                float2 aw0 = *(const float2*)(AW + rb + ni * 8);
                float2 aw1 = *(const float2*)(AW + rb + (size_t)8 * SS + ni * 8);
                float sc00 = c[mi][ni][0] * SCALEF, sc01 = c[mi][ni][1] * SCALEF;
                float sc10 = c[mi][ni][2] * SCALEF, sc11 = c[mi][ni][3] * SCALEF;
                ssum[mi * 2]     += __expf(sc00) + __expf(sc01);
                ssum[mi * 2 + 1] += __expf(sc10) + __expf(sc11);
                usum[mi * 2]     += __expf(sc00 + aw0.x) + __expf(sc01 + aw0.y);
                usum[mi * 2 + 1] += __expf(sc10 + aw1.x) + __expf(sc11 + aw1.y);
            }
        }
        CPA_WAIT(0);
        __syncthreads();
    }

    #pragma unroll
    for (int sl = 0; sl < 4; sl++) {
        ssum[sl] += __shfl_xor_sync(~0u, ssum[sl], 1);
        ssum[sl] += __shfl_xor_sync(~0u, ssum[sl], 2);
        usum[sl] += __shfl_xor_sync(~0u, usum[sl], 1);
        usum[sl] += __shfl_xor_sync(~0u, usum[sl], 2);
    }
    if ((lane & 3) == 0) {
        #pragma unroll
        for (int sl = 0; sl < 4; sl++) {
            const int row = wm * 32 + (sl >> 1) * 16 + qr + 8 * (sl & 1);
            redS[wn * 64 + row] = ssum[sl];
            redU[wn * 64 + row] = usum[sl];
        }
    }
    __syncthreads();
    if (tid < 64) {
        float st = redS[tid] + redS[64 + tid] + redS[128 + tid] + redS[192 + tid];
        float ut = redU[tid] + redU[64 + tid] + redU[128 + tid] + redU[192 + tid];
        const int gi = bh * NN + q0 + tid;
        g_lse[gi] = __logf(st);
        g_isu[gi] = 1.0f / ut;
    }
}

// ============================================================================
// Pass 2: 256-thread CTA, 64 q-rows x 64-col s-chunks (16), 2 CTAs/SM.
// smem: Q(2) + K dbuf(4) + V(2) + P(2), all 64x64 tiles = 10*9216 = 92160 B.
// warp grid 2(m) x 4(n); QK warp tile 32x16; PV warp tile 32x16.
// ============================================================================
__global__ void __launch_bounds__(256, 2) attn_av(const float* __restrict__ AW,
                                                  float* __restrict__ LOGOUT) {
    extern __shared__ char sm[];
    const uint32_t s0 = smem_u32(sm);
    const uint32_t sQH = s0, sQL = s0 + QTILEB;
    const uint32_t kBase = s0 + 2 * QTILEB;               // 4 x QTILEB (2 bufs x hi/lo)
    const uint32_t sVH = s0 + 6 * QTILEB, sVL = s0 + 7 * QTILEB;
    const uint32_t pH = s0 + 8 * QTILEB, pL = s0 + 9 * QTILEB;

    const int tid = threadIdx.x, lane = tid & 31, wid = tid >> 5;
    const int wm = wid & 1, wn = wid >> 1;
    const int bh = blockIdx.y;
    const int q0 = blockIdx.x * 64;
    const int qr = lane >> 2, qc = (lane & 3) * 2;

    const size_t qbase = ((size_t)bh * NN + q0) * DD;
    const size_t kvbase = (size_t)bh * SS * DD;

    cpa_t64_256(sQH, sQL, g_Qh, g_Ql, qbase, tid);
    cpa_t64_256(kBase, kBase + QTILEB, g_Kh, g_Kl, kvbase, tid);
    CPA_COMMIT(); CPA_WAIT(0);
    __syncthreads();

    float lse_r[4], isu_r[4];
    #pragma unroll
    for (int sl = 0; sl < 4; sl++) {
        const int row = q0 + wm * 32 + (sl >> 1) * 16 + qr + 8 * (sl & 1);
        lse_r[sl] = g_lse[bh * NN + row];
        isu_r[sl] = g_isu[bh * NN + row];
    }

    float c2[2][2][4] = {};

    for (int sc = 0; sc < 16; sc++) {
        const int buf = sc & 1;
        // group: V(sc)
        cpa_t64_256(sVH, sVL, g_Vh, g_Vl, kvbase + (size_t)sc * 64 * DD, tid);
        CPA_COMMIT();
        if (sc < 15) {
            const uint32_t kb = kBase + (buf ^ 1) * 2 * QTILEB;
            cpa_t64_256(kb, kb + QTILEB, g_Kh, g_Kl, kvbase + (size_t)(sc + 1) * 64 * DD, tid);
            CPA_COMMIT();
        }
        const uint32_t kH = kBase + buf * 2 * QTILEB, kL = kH + QTILEB;

        // ---- QK: 64x64 tile; warp tile 32x16
        float c[2][2][4] = {};
        #pragma unroll
        for (int ks = 0; ks < 4; ks++) {
            uint32_t ah[2][4], al[2][4], bh2[2][2], bl2[2][2];
            #pragma unroll
            for (int mi = 0; mi < 2; mi++) {
                uint32_t off = ((wm * 32 + mi * 16 + (lane & 15)) * LDT + ks * 16 + (lane >> 4) * 8) * 2;
                ldsm_x4(ah[mi], sQH + off);
                ldsm_x4(al[mi], sQL + off);
            }
            #pragma unroll
            for (int ni = 0; ni < 2; ni++) {
                uint32_t off = ((wn * 16 + ni * 8 + (lane & 7)) * LDT + ks * 16 + ((lane >> 3) & 1) * 8) * 2;
                ldsm_x2(bh2[ni], kH + off);
                ldsm_x2(bl2[ni], kL + off);
            }
            #pragma unroll
            for (int mi = 0; mi < 2; mi++)
                #pragma unroll
                for (int ni = 0; ni < 2; ni++) {
                    mma_bf16(c[mi][ni], ah[mi], bh2[ni]);
                    mma_bf16(c[mi][ni], ah[mi], bl2[ni]);
                    mma_bf16(c[mi][ni], al[mi], bh2[ni]);
                }
        }

        if (sc < 15) { CPA_WAIT(1); } else { CPA_WAIT(0); }
        __syncthreads();   // V visible; P region free

        // ---- softmax + logits + split-P store (AW direct LDG)
        #pragma unroll
        for (int mi = 0; mi < 2; mi++) {
            const int prow0 = wm * 32 + mi * 16 + qr;
            const size_t rbb = ((size_t)bh * NN + q0 + prow0) * SS + sc * 64;
            #pragma unroll
            for (int ni = 0; ni < 2; ni++) {
                const int col = wn * 16 + ni * 8 + qc;
                const size_t rb = rbb + col;
                float2 aw0 = *(const float2*)(AW + rb);
                float2 aw1 = *(const float2*)(AW + rb + (size_t)8 * SS);
                float u00 = fmaf(c[mi][ni][0], SCALEF, aw0.x);
                float u01 = fmaf(c[mi][ni][1], SCALEF, aw0.y);
                float u10 = fmaf(c[mi][ni][2], SCALEF, aw1.x);
                float u11 = fmaf(c[mi][ni][3], SCALEF, aw1.y);
                const int sl0 = mi * 2, sl1 = mi * 2 + 1;
                *(float2*)(LOGOUT + rb) = make_float2(u00 - lse_r[sl0], u01 - lse_r[sl0]);
                *(float2*)(LOGOUT + rb + (size_t)8 * SS) = make_float2(u10 - lse_r[sl1], u11 - lse_r[sl1]);
                float p00 = __expf(u00) * isu_r[sl0], p01 = __expf(u01) * isu_r[sl0];
                float p10 = __expf(u10) * isu_r[sl1], p11 = __expf(u11) * isu_r[sl1];
                *(uint32_t*)(sm + (pH - s0) + (prow0 * LDT + col) * 2)       = packbf(p00, p01);
                *(uint32_t*)(sm + (pH - s0) + ((prow0 + 8) * LDT + col) * 2) = packbf(p10, p11);
                *(uint32_t*)(sm + (pL - s0) + (prow0 * LDT + col) * 2)       = packbf(bflo(p00), bflo(p01));
                *(uint32_t*)(sm + (pL - s0) + ((prow0 + 8) * LDT + col) * 2) = packbf(bflo(p10), bflo(p11));
            }
        }
        __syncthreads();   // P visible

        // ---- PV: O[64x64] += P[64x64] @ V[64x64], warp tile 32x16
        #pragma unroll
        for (int ksp = 0; ksp < 4; ksp++) {
            uint32_t pa[2][4], pe[2][4], vh[2][2], vl[2][2];
            #pragma unroll
            for (int mi = 0; mi < 2; mi++) {
                uint32_t off = ((wm * 32 + mi * 16 + (lane & 15)) * LDT + ksp * 16 + (lane >> 4) * 8) * 2;
                ldsm_x4(pa[mi], pH + off);
                ldsm_x4(pe[mi], pL + off);
            }
            #pragma unroll
            for (int nj = 0; nj < 2; nj++) {
                uint32_t off = ((ksp * 16 + (lane & 15)) * LDT + wn * 16 + nj * 8) * 2;
                ldsm_x2t(vh[nj], sVH + off);
                ldsm_x2t(vl[nj], sVL + off);
            }
            #pragma unroll
            for (int mi = 0; mi < 2; mi++)
                #pragma unroll
                for (int nj = 0; nj < 2; nj++) {
                    mma_bf16(c2[mi][nj], pa[mi], vh[nj]);
                    mma_bf16(c2[mi][nj], pa[mi], vl[nj]);
                    mma_bf16(c2[mi][nj], pe[mi], vh[nj]);
                }
        }
        CPA_WAIT(0);
        __syncthreads();   // K swap + V/P reuse safe
    }

    const int b = bh / HH, h = bh % HH;
    #pragma unroll
    for (int mi = 0; mi < 2; mi++)
        #pragma unroll
        for (int nj = 0; nj < 2; nj++) {
            const int row = q0 + wm * 32 + mi * 16 + qr;
            const int col = h * DD + wn * 16 + nj * 8 + qc;
            const size_t o0 = (size_t)(b * NN + row) * CC + col;
            const size_t o1 = (size_t)(b * NN + row + 8) * CC + col;
            float x0 = c2[mi][nj][0], x1 = c2[mi][nj][1];
            float x2 = c2[mi][nj][2], x3 = c2[mi][nj][3];
            *(uint32_t*)(g_AOh + o0) = packbf(x0, x1);
            *(uint32_t*)(g_AOh + o1) = packbf(x2, x3);
            *(uint32_t*)(g_AOl + o0) = packbf(bflo(x0), bflo(x1));
            *(uint32_t*)(g_AOl + o1) = packbf(bflo(x2), bflo(x3));
        }
}

// ============================================================================
extern "C" void kernel_launch(void* const* d_in, const int* in_sizes, int n_in,
                              void* d_out, int out_size) {
    const float* query = (const float*)d_in[0];
    const float* key_  = (const float*)d_in[1];
    const float* value = (const float*)d_in[2];
    const float* aw    = (const float*)d_in[3];
    const float* Wq    = (const float*)d_in[4];
    const float* Wk    = (const float*)d_in[5];
    const float* Wv    = (const float*)d_in[6];
    const float* Wo    = (const float*)d_in[7];
    const float* bo    = (const float*)d_in[8];

    float* out    = (float*)d_out;                       // [B,N,C]
    float* logout = out + (size_t)BB * NN * CC;          // [B,H,N,S]

    const int smem_gemm  = 2 * GBUF;                      // 110592
    const int smem_stats = 2 * QTILEB + 4 * TILEB + 2048; // 94208
    const int smem_av    = 10 * QTILEB;                   // 92160
    cudaFuncSetAttribute(tc_gemm_qkv, cudaFuncAttributeMaxDynamicSharedMemorySize, smem_gemm);
    cudaFuncSetAttribute(tc_gemm_out, cudaFuncAttributeMaxDynamicSharedMemorySize, smem_gemm);
    cudaFuncSetAttribute(attn_stats,  cudaFuncAttributeMaxDynamicSharedMemorySize, smem_stats);
    cudaFuncSetAttribute(attn_av,     cudaFuncAttributeMaxDynamicSharedMemorySize, smem_av);

    const int nX4 = (BB * NN * CC) / 4;
    const int nW4 = (CC * CC) / 4;
    dim3 gsx((nX4 + 255) / 256, 1, 3);
    dim3 gsw((nW4 + 255) / 256, 1, 4);
    dim3 gqkv(CC / 64, (BB * NN) / 128, 3);    // 12 x 64 x 3
    dim3 gp(CC / 64, (BB * NN) / 128);         // 12 x 64
    dim3 gst(NN / 64, BB * HH);                // 16 x 96
    dim3 gav(NN / 64, BB * HH);                // 16 x 96

    split_x3<<<gsx, 256>>>(query, key_, value, nX4);
    split_w4<<<gsw, 256>>>(Wq, Wk, Wv, Wo, nW4);
    tc_gemm_qkv<<<gqkv, 256, smem_gemm>>>();
    attn_stats<<<gst, 256, smem_stats>>>(aw);
    attn_av<<<gav, 256, smem_av>>>(aw, logout);
    tc_gemm_out<<<gp, 256, smem_gemm>>>(bo, out);
}

// round 14
// speedup vs baseline: 1.3967x; 1.2462x over previous
#include <cuda_runtime.h>
#include <cuda_fp16.h>
#include <math.h>
#include <stdint.h>

#define BB 8
#define NN 1024
#define SS 1024
#define CC 768
#define HH 12
#define DD 64
#define SCALEF 0.125f

#define LDT 72        // fp16 elems per 64-wide tile row (144B, conflict-free)
#define TILEB (128 * LDT * 2)   // 18432 B per 128x64 fp16 tile
#define QTILEB (64 * LDT * 2)   // 9216 B per 64x64 fp16 tile
#define ATILE 18432
#define BTILE 9216
#define GBUF (ATILE + 2 * BTILE)   // 36864 per gemm buffer (A hi + B hi/lo)

// -------- scratch (device globals; no allocation allowed) --------
__device__ __align__(256) __half g_xq_h[(size_t)BB * NN * CC];
__device__ __align__(256) __half g_xk_h[(size_t)BB * SS * CC];
__device__ __align__(256) __half g_xv_h[(size_t)BB * SS * CC];
__device__ __align__(256) __half g_wq_h[(size_t)CC * CC];
__device__ __align__(256) __half g_wq_l[(size_t)CC * CC];
__device__ __align__(256) __half g_wk_h[(size_t)CC * CC];
__device__ __align__(256) __half g_wk_l[(size_t)CC * CC];
__device__ __align__(256) __half g_wv_h[(size_t)CC * CC];
__device__ __align__(256) __half g_wv_l[(size_t)CC * CC];
__device__ __align__(256) __half g_wo_h[(size_t)CC * CC];
__device__ __align__(256) __half g_wo_l[(size_t)CC * CC];
__device__ __align__(256) __half g_Qh[(size_t)BB * HH * NN * DD];
__device__ __align__(256) __half g_Kh[(size_t)BB * HH * SS * DD];
__device__ __align__(256) __half g_Kl[(size_t)BB * HH * SS * DD];
__device__ __align__(256) __half g_Vh[(size_t)BB * HH * SS * DD];
__device__ __align__(256) __half g_Vl[(size_t)BB * HH * SS * DD];
__device__ __align__(256) __half g_AOh[(size_t)BB * NN * CC];
__device__ float g_lse[BB * HH * NN];
__device__ float g_isu[BB * HH * NN];

// ============================================================================
// helpers
// ============================================================================
__device__ __forceinline__ uint32_t smem_u32(const void* p) {
    uint32_t a;
    asm("{ .reg .u64 t; cvta.to.shared.u64 t, %1; cvt.u32.u64 %0, t; }" : "=r"(a) : "l"(p));
    return a;
}
__device__ __forceinline__ void mma_f16(float* c, const uint32_t* a, const uint32_t* b) {
    asm volatile("mma.sync.aligned.m16n8k16.row.col.f32.f16.f16.f32 "
        "{%0,%1,%2,%3}, {%4,%5,%6,%7}, {%8,%9}, {%0,%1,%2,%3};"
        : "+f"(c[0]), "+f"(c[1]), "+f"(c[2]), "+f"(c[3])
        : "r"(a[0]), "r"(a[1]), "r"(a[2]), "r"(a[3]), "r"(b[0]), "r"(b[1]));
}
__device__ __forceinline__ void ldsm_x4(uint32_t* r, uint32_t a) {
    asm volatile("ldmatrix.sync.aligned.m8n8.x4.shared.b16 {%0,%1,%2,%3}, [%4];"
        : "=r"(r[0]), "=r"(r[1]), "=r"(r[2]), "=r"(r[3]) : "r"(a));
}
__device__ __forceinline__ void ldsm_x2(uint32_t* r, uint32_t a) {
    asm volatile("ldmatrix.sync.aligned.m8n8.x2.shared.b16 {%0,%1}, [%2];"
        : "=r"(r[0]), "=r"(r[1]) : "r"(a));
}
__device__ __forceinline__ void ldsm_x2t(uint32_t* r, uint32_t a) {
    asm volatile("ldmatrix.sync.aligned.m8n8.x2.trans.shared.b16 {%0,%1}, [%2];"
        : "=r"(r[0]), "=r"(r[1]) : "r"(a));
}
#define CPA16(dst, src) \
    asm volatile("cp.async.cg.shared.global [%0], [%1], 16;" :: "r"(dst), "l"(src) : "memory")
#define CPA_COMMIT() asm volatile("cp.async.commit_group;" ::: "memory")
#define CPA_WAIT(n)  asm volatile("cp.async.wait_group %0;" :: "n"(n) : "memory")

__device__ __forceinline__ uint32_t packh(float x, float y) {
    __half2 t = __halves2half2(__float2half(x), __float2half(y));
    return *(uint32_t*)&t;
}
__device__ __forceinline__ float hlo(float x) {
    return x - __half2float(__float2half(x));
}

// ============================================================================
// fp32 -> fp16 splits
// ============================================================================
__device__ __forceinline__ void split_hi(const float* __restrict__ x,
                                         __half* __restrict__ hi, int i) {
    float4 v = *(const float4*)(x + (size_t)i * 4);
    *(uint32_t*)(hi + (size_t)i * 4)     = packh(v.x, v.y);
    *(uint32_t*)(hi + (size_t)i * 4 + 2) = packh(v.z, v.w);
}
__device__ __forceinline__ void split_hl(const float* __restrict__ x,
                                         __half* __restrict__ hi,
                                         __half* __restrict__ lo, int i) {
    float4 v = *(const float4*)(x + (size_t)i * 4);
    *(uint32_t*)(hi + (size_t)i * 4)     = packh(v.x, v.y);
    *(uint32_t*)(hi + (size_t)i * 4 + 2) = packh(v.z, v.w);
    *(uint32_t*)(lo + (size_t)i * 4)     = packh(hlo(v.x), hlo(v.y));
    *(uint32_t*)(lo + (size_t)i * 4 + 2) = packh(hlo(v.z), hlo(v.w));
}

__global__ void split_x3(const float* __restrict__ xq, const float* __restrict__ xk,
                         const float* __restrict__ xv, int n4) {
    int i = blockIdx.x * blockDim.x + threadIdx.x;
    if (i >= n4) return;
    if (blockIdx.z == 0)      split_hi(xq, g_xq_h, i);
    else if (blockIdx.z == 1) split_hi(xk, g_xk_h, i);
    else                      split_hi(xv, g_xv_h, i);
}
__global__ void split_w4(const float* __restrict__ wq, const float* __restrict__ wk,
                         const float* __restrict__ wv, const float* __restrict__ wo, int n4) {
    int i = blockIdx.x * blockDim.x + threadIdx.x;
    if (i >= n4) return;
    if (blockIdx.z == 0)      split_hl(wq, g_wq_h, g_wq_l, i);
    else if (blockIdx.z == 1) split_hl(wk, g_wk_h, g_wk_l, i);
    else if (blockIdx.z == 2) split_hl(wv, g_wv_h, g_wv_l, i);
    else                      split_hl(wo, g_wo_h, g_wo_l, i);
}

// ============================================================================
// GEMM mainloop, 256 threads, 128x64 output tile, double-buffered cp.async.
// c[2][4][4] += Xh[128 x CC] . (Wh+Wl)[64 x CC]^T  (2-term fp16).
// warp grid 4(m) x 2(n), warp tile 32x32.
// ============================================================================
__device__ __forceinline__ void gemm_mainloop256(
    const __half* __restrict__ Xh,
    const __half* __restrict__ Wh, const __half* __restrict__ Wl,
    int m0, int n0, uint32_t s0, int tid, int lane, int wm, int wn,
    float c[2][4][4]) {
    auto issue = [&](int ch, int buf) {
        const uint32_t base = s0 + buf * GBUF;
        #pragma unroll
        for (int t = 0; t < 4; t++) {
            const int id = tid + 256 * t, row = id >> 3, seg = id & 7;
            const uint32_t doff = (uint32_t)(row * LDT + seg * 8) * 2;
            const size_t sx = (size_t)(m0 + row) * CC + ch * 64 + seg * 8;
            CPA16(base + doff, Xh + sx);
        }
        #pragma unroll
        for (int t = 0; t < 2; t++) {
            const int id = tid + 256 * t, row = id >> 3, seg = id & 7;
            const uint32_t doff = (uint32_t)(row * LDT + seg * 8) * 2;
            const size_t sw = (size_t)(n0 + row) * CC + ch * 64 + seg * 8;
            CPA16(base + ATILE + doff, Wh + sw);
            CPA16(base + ATILE + BTILE + doff, Wl + sw);
        }
    };
    issue(0, 0); CPA_COMMIT(); CPA_WAIT(0);
    __syncthreads();
    int buf = 0;
    for (int ch = 0; ch < 12; ch++) {
        if (ch < 11) { issue(ch + 1, buf ^ 1); CPA_COMMIT(); }
        const uint32_t aH = s0 + buf * GBUF;
        const uint32_t bH = aH + ATILE, bL = bH + BTILE;
        #pragma unroll
        for (int ks = 0; ks < 4; ks++) {
            uint32_t ah[2][4], bh[4][2], bl[4][2];
            #pragma unroll
            for (int mi = 0; mi < 2; mi++) {
                uint32_t off = ((wm * 32 + mi * 16 + (lane & 15)) * LDT + ks * 16 + (lane >> 4) * 8) * 2;
                ldsm_x4(ah[mi], aH + off);
            }
            #pragma unroll
            for (int ni = 0; ni < 4; ni++) {
                uint32_t off = ((wn * 32 + ni * 8 + (lane & 7)) * LDT + ks * 16 + ((lane >> 3) & 1) * 8) * 2;
                ldsm_x2(bh[ni], bH + off);
                ldsm_x2(bl[ni], bL + off);
            }
            #pragma unroll
            for (int mi = 0; mi < 2; mi++)
                #pragma unroll
                for (int ni = 0; ni < 4; ni++) {
                    mma_f16(c[mi][ni], ah[mi], bh[ni]);
                    mma_f16(c[mi][ni], ah[mi], bl[ni]);
                }
        }
        CPA_WAIT(0);
        __syncthreads();
        buf ^= 1;
    }
}

// QKV projections merged: grid.z selects tensor; head-major output.
// Q: hi only.  K, V: hi + lo (they are B-operands downstream).
__global__ void __launch_bounds__(256, 2) tc_gemm_qkv() {
    extern __shared__ char sm[];
    const uint32_t s0 = smem_u32(sm);
    const int tid = threadIdx.x, lane = tid & 31, wid = tid >> 5;
    const int wm = wid & 3, wn = wid >> 2;
    const int m0 = blockIdx.y * 128, n0 = blockIdx.x * 64, z = blockIdx.z;
    const __half *Xh, *Wh, *Wl;
    __half *Yh, *Yl;
    if (z == 0)      { Xh = g_xq_h; Wh = g_wq_h; Wl = g_wq_l; Yh = g_Qh; Yl = nullptr; }
    else if (z == 1) { Xh = g_xk_h; Wh = g_wk_h; Wl = g_wk_l; Yh = g_Kh; Yl = g_Kl; }
    else             { Xh = g_xv_h; Wh = g_wv_h; Wl = g_wv_l; Yh = g_Vh; Yl = g_Vl; }

    float c[2][4][4] = {};
    gemm_mainloop256(Xh, Wh, Wl, m0, n0, s0, tid, lane, wm, wn, c);

    const int qr = lane >> 2, qc = (lane & 3) * 2;
    #pragma unroll
    for (int mi = 0; mi < 2; mi++)
        #pragma unroll
        for (int ni = 0; ni < 4; ni++) {
            const int rowg = m0 + wm * 32 + mi * 16 + qr;
            const int b = rowg >> 10, r = rowg & 1023;
            const int col = n0 + wn * 32 + ni * 8 + qc;
            const int h = col >> 6, d = col & 63;
            const size_t o0 = ((size_t)(b * HH + h) * NN + r) * DD + d;
            const size_t o1 = o0 + (size_t)8 * DD;
            float x0 = c[mi][ni][0], x1 = c[mi][ni][1];
            float x2 = c[mi][ni][2], x3 = c[mi][ni][3];
            *(uint32_t*)(Yh + o0) = packh(x0, x1);
            *(uint32_t*)(Yh + o1) = packh(x2, x3);
            if (Yl) {
                *(uint32_t*)(Yl + o0) = packh(hlo(x0), hlo(x1));
                *(uint32_t*)(Yl + o1) = packh(hlo(x2), hlo(x3));
            }
        }
}

// output projection: AOh @ (Wo hi+lo) + bo -> fp32
__global__ void __launch_bounds__(256, 2) tc_gemm_out(const float* __restrict__ bias,
                                                      float* __restrict__ Yf) {
    extern __shared__ char sm[];
    const uint32_t s0 = smem_u32(sm);
    const int tid = threadIdx.x, lane = tid & 31, wid = tid >> 5;
    const int wm = wid & 3, wn = wid >> 2;
    const int m0 = blockIdx.y * 128, n0 = blockIdx.x * 64;

    float c[2][4][4] = {};
    gemm_mainloop256(g_AOh, g_wo_h, g_wo_l, m0, n0, s0, tid, lane, wm, wn, c);

    const int qr = lane >> 2, qc = (lane & 3) * 2;
    #pragma unroll
    for (int mi = 0; mi < 2; mi++)
        #pragma unroll
        for (int ni = 0; ni < 4; ni++) {
            const int row = m0 + wm * 32 + mi * 16 + qr;
            const int col = n0 + wn * 32 + ni * 8 + qc;
            *(float2*)(Yf + (size_t)row * CC + col) =
                make_float2(c[mi][ni][0] + bias[col], c[mi][ni][1] + bias[col + 1]);
            *(float2*)(Yf + (size_t)(row + 8) * CC + col) =
                make_float2(c[mi][ni][2] + bias[col], c[mi][ni][3] + bias[col + 1]);
        }
}

// tile copies (256 threads): single tile, 64 or 128 rows
__device__ __forceinline__ void cpa_s64(uint32_t d, const __half* __restrict__ s,
                                        size_t base, int tid) {
    #pragma unroll
    for (int t = 0; t < 2; t++) {
        const int id = tid + 256 * t, row = id >> 3, seg = id & 7;
        CPA16(d + (uint32_t)(row * LDT + seg * 8) * 2, s + base + (size_t)row * 64 + seg * 8);
    }
}
__device__ __forceinline__ void cpa_p64(uint32_t dhi, uint32_t dlo,
                                        const __half* __restrict__ shi,
                                        const __half* __restrict__ slo,
                                        size_t base, int tid) {
    #pragma unroll
    for (int t = 0; t < 2; t++) {
        const int id = tid + 256 * t, row = id >> 3, seg = id & 7;
        const uint32_t doff = (uint32_t)(row * LDT + seg * 8) * 2;
        const size_t s = base + (size_t)row * 64 + seg * 8;
        CPA16(dhi + doff, shi + s);
        CPA16(dlo + doff, slo + s);
    }
}
__device__ __forceinline__ void cpa_p128(uint32_t dhi, uint32_t dlo,
                                         const __half* __restrict__ shi,
                                         const __half* __restrict__ slo,
                                         size_t base, int tid) {
    #pragma unroll
    for (int t = 0; t < 4; t++) {
        const int id = tid + 256 * t, row = id >> 3, seg = id & 7;
        const uint32_t doff = (uint32_t)(row * LDT + seg * 8) * 2;
        const size_t s = base + (size_t)row * 64 + seg * 8;
        CPA16(dhi + doff, shi + s);
        CPA16(dlo + doff, slo + s);
    }
}

// ============================================================================
// Pass 1: 256-thread CTA over 64 q-rows, 2 CTAs/SM. fp16 2-term QK.
// smem: Q(9216) + K dbuf(4x18432) + red(2048) = 84992 B.
// ============================================================================
__global__ void __launch_bounds__(256, 2) attn_stats(const float* __restrict__ AW) {
    extern __shared__ char sm[];
    const uint32_t s0 = smem_u32(sm);
    const uint32_t sQH = s0;
    const uint32_t kBase = s0 + QTILEB;
    float* redS = (float*)(sm + QTILEB + 4 * TILEB);
    float* redU = redS + 4 * 64;

    const int tid = threadIdx.x, lane = tid & 31, wid = tid >> 5;
    const int wm = wid & 1, wn = wid >> 1;
    const int bh = blockIdx.y;
    const int q0 = blockIdx.x * 64;
    const int qr = lane >> 2, qc = (lane & 3) * 2;

    const size_t qbase = ((size_t)bh * NN + q0) * DD;
    const size_t kbase0 = (size_t)bh * SS * DD;

    cpa_s64(sQH, g_Qh, qbase, tid);
    cpa_p128(kBase, kBase + TILEB, g_Kh, g_Kl, kbase0, tid);
    CPA_COMMIT(); CPA_WAIT(0);
    __syncthreads();

    float ssum[4] = {}, usum[4] = {};

    for (int sc = 0; sc < 8; sc++) {
        const int buf = sc & 1;
        if (sc < 7) {
            const uint32_t kb = kBase + (buf ^ 1) * 2 * TILEB;
            cpa_p128(kb, kb + TILEB, g_Kh, g_Kl, kbase0 + (size_t)(sc + 1) * 128 * DD, tid);
            CPA_COMMIT();
        }
        const uint32_t kH = kBase + buf * 2 * TILEB, kL = kH + TILEB;

        float c[2][4][4] = {};
        #pragma unroll
        for (int ks = 0; ks < 4; ks++) {
            uint32_t ah[2][4], bh2[4][2], bl2[4][2];
            #pragma unroll
            for (int mi = 0; mi < 2; mi++) {
                uint32_t off = ((wm * 32 + mi * 16 + (lane & 15)) * LDT + ks * 16 + (lane >> 4) * 8) * 2;
                ldsm_x4(ah[mi], sQH + off);
            }
            #pragma unroll
            for (int ni = 0; ni < 4; ni++) {
                uint32_t off = ((wn * 32 + ni * 8 + (lane & 7)) * LDT + ks * 16 + ((lane >> 3) & 1) * 8) * 2;
                ldsm_x2(bh2[ni], kH + off);
                ldsm_x2(bl2[ni], kL + off);
            }
            #pragma unroll
            for (int mi = 0; mi < 2; mi++)
                #pragma unroll
                for (int ni = 0; ni < 4; ni++) {
                    mma_f16(c[mi][ni], ah[mi], bh2[ni]);
                    mma_f16(c[mi][ni], ah[mi], bl2[ni]);
                }
        }

        const int s0c = sc * 128;
        #pragma unroll
        for (int mi = 0; mi < 2; mi++) {
            const size_t rb = ((size_t)bh * NN + q0 + wm * 32 + mi * 16 + qr) * SS + s0c + wn * 32 + qc;
            #pragma unroll
            for (int ni = 0; ni < 4; ni++) {
                float2 aw0 = *(const float2*)(AW + rb + ni * 8);
                float2 aw1 = *(const float2*)(AW + rb + (size_t)8 * SS + ni * 8);
                float sc00 = c[mi][ni][0] * SCALEF, sc01 = c[mi][ni][1] * SCALEF;
                float sc10 = c[mi][ni][2] * SCALEF, sc11 = c[mi][ni][3] * SCALEF;
                ssum[mi * 2]     += __expf(sc00) + __expf(sc01);
                ssum[mi * 2 + 1] += __expf(sc10) + __expf(sc11);
                usum[mi * 2]     += __expf(sc00 + aw0.x) + __expf(sc01 + aw0.y);
                usum[mi * 2 + 1] += __expf(sc10 + aw1.x) + __expf(sc11 + aw1.y);
            }
        }
        CPA_WAIT(0);
        __syncthreads();
    }

    #pragma unroll
    for (int sl = 0; sl < 4; sl++) {
        ssum[sl] += __shfl_xor_sync(~0u, ssum[sl], 1);
        ssum[sl] += __shfl_xor_sync(~0u, ssum[sl], 2);
        usum[sl] += __shfl_xor_sync(~0u, usum[sl], 1);
        usum[sl] += __shfl_xor_sync(~0u, usum[sl], 2);
    }
    if ((lane & 3) == 0) {
        #pragma unroll
        for (int sl = 0; sl < 4; sl++) {
            const int row = wm * 32 + (sl >> 1) * 16 + qr + 8 * (sl & 1);
            redS[wn * 64 + row] = ssum[sl];
            redU[wn * 64 + row] = usum[sl];
        }
    }
    __syncthreads();
    if (tid < 64) {
        float st = redS[tid] + redS[64 + tid] + redS[128 + tid] + redS[192 + tid];
        float ut = redU[tid] + redU[64 + tid] + redU[128 + tid] + redU[192 + tid];
        const int gi = bh * NN + q0 + tid;
        g_lse[gi] = __logf(st);
        g_isu[gi] = 1.0f / ut;
    }
}

// ============================================================================
// Pass 2: 256-thread CTA, 64 q-rows x 64-col s-chunks (16), 2 CTAs/SM.
// fp16: QK 2-term, P single fp16, PV 2-term (V hi+lo).
// smem: Q(1) + K dbuf(4) + V(2) + P(1) = 8*9216 = 73728 B.
// ============================================================================
__global__ void __launch_bounds__(256, 2) attn_av(const float* __restrict__ AW,
                                                  float* __restrict__ LOGOUT) {
    extern __shared__ char sm[];
    const uint32_t s0 = smem_u32(sm);
    const uint32_t sQH = s0;
    const uint32_t kBase = s0 + QTILEB;                   // 4 x QTILEB
    const uint32_t sVH = s0 + 5 * QTILEB, sVL = s0 + 6 * QTILEB;
    const uint32_t pH = s0 + 7 * QTILEB;

    const int tid = threadIdx.x, lane = tid & 31, wid = tid >> 5;
    const int wm = wid & 1, wn = wid >> 1;
    const int bh = blockIdx.y;
    const int q0 = blockIdx.x * 64;
    const int qr = lane >> 2, qc = (lane & 3) * 2;

    const size_t qbase = ((size_t)bh * NN + q0) * DD;
    const size_t kvbase = (size_t)bh * SS * DD;

    cpa_s64(sQH, g_Qh, qbase, tid);
    cpa_p64(kBase, kBase + QTILEB, g_Kh, g_Kl, kvbase, tid);
    CPA_COMMIT(); CPA_WAIT(0);
    __syncthreads();

    float lse_r[4], isu_r[4];
    #pragma unroll
    for (int sl = 0; sl < 4; sl++) {
        const int row = q0 + wm * 32 + (sl >> 1) * 16 + qr + 8 * (sl & 1);
        lse_r[sl] = g_lse[bh * NN + row];
        isu_r[sl] = g_isu[bh * NN + row];
    }

    float c2[2][2][4] = {};

    for (int sc = 0; sc < 16; sc++) {
        const int buf = sc & 1;
        cpa_p64(sVH, sVL, g_Vh, g_Vl, kvbase + (size_t)sc * 64 * DD, tid);
        CPA_COMMIT();
        if (sc < 15) {
            const uint32_t kb = kBase + (buf ^ 1) * 2 * QTILEB;
            cpa_p64(kb, kb + QTILEB, g_Kh, g_Kl, kvbase + (size_t)(sc + 1) * 64 * DD, tid);
            CPA_COMMIT();
        }
        const uint32_t kH = kBase + buf * 2 * QTILEB, kL = kH + QTILEB;

        // ---- QK: 64x64 tile; warp tile 32x16, 2-term
        float c[2][2][4] = {};
        #pragma unroll
        for (int ks = 0; ks < 4; ks++) {
            uint32_t ah[2][4], bh2[2][2], bl2[2][2];
            #pragma unroll
            for (int mi = 0; mi < 2; mi++) {
                uint32_t off = ((wm * 32 + mi * 16 + (lane & 15)) * LDT + ks * 16 + (lane >> 4) * 8) * 2;
                ldsm_x4(ah[mi], sQH + off);
            }
            #pragma unroll
            for (int ni = 0; ni < 2; ni++) {
                uint32_t off = ((wn * 16 + ni * 8 + (lane & 7)) * LDT + ks * 16 + ((lane >> 3) & 1) * 8) * 2;
                ldsm_x2(bh2[ni], kH + off);
                ldsm_x2(bl2[ni], kL + off);
            }
            #pragma unroll
            for (int mi = 0; mi < 2; mi++)
                #pragma unroll
                for (int ni = 0; ni < 2; ni++) {
                    mma_f16(c[mi][ni], ah[mi], bh2[ni]);
                    mma_f16(c[mi][ni], ah[mi], bl2[ni]);
                }
        }

        if (sc < 15) { CPA_WAIT(1); } else { CPA_WAIT(0); }
        __syncthreads();   // V visible; P region free

        // ---- softmax + logits + P store (fp16, AW direct LDG)
        #pragma unroll
        for (int mi = 0; mi < 2; mi++) {
            const int prow0 = wm * 32 + mi * 16 + qr;
            const size_t rbb = ((size_t)bh * NN + q0 + prow0) * SS + sc * 64;
            #pragma unroll
            for (int ni = 0; ni < 2; ni++) {
                const int col = wn * 16 + ni * 8 + qc;
                const size_t rb = rbb + col;
                float2 aw0 = *(const float2*)(AW + rb);
                float2 aw1 = *(const float2*)(AW + rb + (size_t)8 * SS);
                float u00 = fmaf(c[mi][ni][0], SCALEF, aw0.x);
                float u01 = fmaf(c[mi][ni][1], SCALEF, aw0.y);
                float u10 = fmaf(c[mi][ni][2], SCALEF, aw1.x);
                float u11 = fmaf(c[mi][ni][3], SCALEF, aw1.y);
                const int sl0 = mi * 2, sl1 = mi * 2 + 1;
                *(float2*)(LOGOUT + rb) = make_float2(u00 - lse_r[sl0], u01 - lse_r[sl0]);
                *(float2*)(LOGOUT + rb + (size_t)8 * SS) = make_float2(u10 - lse_r[sl1], u11 - lse_r[sl1]);
                float p00 = __expf(u00) * isu_r[sl0], p01 = __expf(u01) * isu_r[sl0];
                float p10 = __expf(u10) * isu_r[sl1], p11 = __expf(u11) * isu_r[sl1];
                *(uint32_t*)(sm + (pH - s0) + (prow0 * LDT + col) * 2)       = packh(p00, p01);
                *(uint32_t*)(sm + (pH - s0) + ((prow0 + 8) * LDT + col) * 2) = packh(p10, p11);
            }
        }
        __syncthreads();   // P visible

        // ---- PV: O[64x64] += P[64x64] @ (Vh+Vl)[64x64], warp tile 32x16
        #pragma unroll
        for (int ksp = 0; ksp < 4; ksp++) {
            uint32_t pa[2][4], vh[2][2], vl[2][2];
            #pragma unroll
            for (int mi = 0; mi < 2; mi++) {
                uint32_t off = ((wm * 32 + mi * 16 + (lane & 15)) * LDT + ksp * 16 + (lane >> 4) * 8) * 2;
                ldsm_x4(pa[mi], pH + off);
            }
            #pragma unroll
            for (int nj = 0; nj < 2; nj++) {
                uint32_t off = ((ksp * 16 + (lane & 15)) * LDT + wn * 16 + nj * 8) * 2;
                ldsm_x2t(vh[nj], sVH + off);
                ldsm_x2t(vl[nj], sVL + off);
            }
            #pragma unroll
            for (int mi = 0; mi < 2; mi++)
                #pragma unroll
                for (int nj = 0; nj < 2; nj++) {
                    mma_f16(c2[mi][nj], pa[mi], vh[nj]);
                    mma_f16(c2[mi][nj], pa[mi], vl[nj]);
                }
        }
        CPA_WAIT(0);
        __syncthreads();   // K swap + V/P reuse safe
    }

    const int b = bh / HH, h = bh % HH;
    #pragma unroll
    for (int mi = 0; mi < 2; mi++)
        #pragma unroll
        for (int nj = 0; nj < 2; nj++) {
            const int row = q0 + wm * 32 + mi * 16 + qr;
            const int col = h * DD + wn * 16 + nj * 8 + qc;
            const size_t o0 = (size_t)(b * NN + row) * CC + col;
            const size_t o1 = (size_t)(b * NN + row + 8) * CC + col;
            *(uint32_t*)(g_AOh + o0) = packh(c2[mi][nj][0], c2[mi][nj][1]);
            *(uint32_t*)(g_AOh + o1) = packh(c2[mi][nj][2], c2[mi][nj][3]);
        }
}

// ============================================================================
extern "C" void kernel_launch(void* const* d_in, const int* in_sizes, int n_in,
                              void* d_out, int out_size) {
    const float* query = (const float*)d_in[0];
    const float* key_  = (const float*)d_in[1];
    const float* value = (const float*)d_in[2];
    const float* aw    = (const float*)d_in[3];
    const float* Wq    = (const float*)d_in[4];
    const float* Wk    = (const float*)d_in[5];
    const float* Wv    = (const float*)d_in[6];
    const float* Wo    = (const float*)d_in[7];
    const float* bo    = (const float*)d_in[8];

    float* out    = (float*)d_out;                       // [B,N,C]
    float* logout = out + (size_t)BB * NN * CC;          // [B,H,N,S]

    const int smem_gemm  = 2 * GBUF;                      // 73728
    const int smem_stats = QTILEB + 4 * TILEB + 2048;     // 84992
    const int smem_av    = 8 * QTILEB;                    // 73728
    cudaFuncSetAttribute(tc_gemm_qkv, cudaFuncAttributeMaxDynamicSharedMemorySize, smem_gemm);
    cudaFuncSetAttribute(tc_gemm_out, cudaFuncAttributeMaxDynamicSharedMemorySize, smem_gemm);
    cudaFuncSetAttribute(attn_stats,  cudaFuncAttributeMaxDynamicSharedMemorySize, smem_stats);
    cudaFuncSetAttribute(attn_av,     cudaFuncAttributeMaxDynamicSharedMemorySize, smem_av);

    const int nX4 = (BB * NN * CC) / 4;
    const int nW4 = (CC * CC) / 4;
    dim3 gsx((nX4 + 255) / 256, 1, 3);
    dim3 gsw((nW4 + 255) / 256, 1, 4);
    dim3 gqkv(CC / 64, (BB * NN) / 128, 3);    // 12 x 64 x 3
    dim3 gp(CC / 64, (BB * NN) / 128);         // 12 x 64
    dim3 gst(NN / 64, BB * HH);                // 16 x 96
    dim3 gav(NN / 64, BB * HH);                // 16 x 96

    split_x3<<<gsx, 256>>>(query, key_, value, nX4);
    split_w4<<<gsw, 256>>>(Wq, Wk, Wv, Wo, nW4);
    tc_gemm_qkv<<<gqkv, 256, smem_gemm>>>();
    attn_stats<<<gst, 256, smem_stats>>>(aw);
    attn_av<<<gav, 256, smem_av>>>(aw, logout);
    tc_gemm_out<<<gp, 256, smem_gemm>>>(bo, out);
}

// round 15
// speedup vs baseline: 1.5016x; 1.0751x over previous
#include <cuda_runtime.h>
#include <cuda_fp16.h>
#include <math.h>
#include <stdint.h>

#define BB 8
#define NN 1024
#define SS 1024
#define CC 768
#define HH 12
#define DD 64
#define SCALEF 0.125f

#define LDT 72        // fp16 elems per 64-wide tile row (144B, conflict-free)
#define TILEB (128 * LDT * 2)   // 18432 B per 128x64 fp16 tile
#define QTILEB (64 * LDT * 2)   // 9216 B per 64x64 fp16 tile
#define ATILE 18432
#define BTILE 9216
#define GBUF (ATILE + 2 * BTILE)   // 36864 per gemm buffer (A hi + B hi/lo)

// -------- scratch (device globals; no allocation allowed) --------
__device__ __align__(256) __half g_xq_h[(size_t)BB * NN * CC];
__device__ __align__(256) __half g_xk_h[(size_t)BB * SS * CC];
__device__ __align__(256) __half g_xv_h[(size_t)BB * SS * CC];
__device__ __align__(256) __half g_wq_h[(size_t)CC * CC];
__device__ __align__(256) __half g_wq_l[(size_t)CC * CC];
__device__ __align__(256) __half g_wk_h[(size_t)CC * CC];
__device__ __align__(256) __half g_wk_l[(size_t)CC * CC];
__device__ __align__(256) __half g_wv_h[(size_t)CC * CC];
__device__ __align__(256) __half g_wv_l[(size_t)CC * CC];
__device__ __align__(256) __half g_wo_h[(size_t)CC * CC];
__device__ __align__(256) __half g_wo_l[(size_t)CC * CC];
__device__ __align__(256) __half g_Qh[(size_t)BB * HH * NN * DD];
__device__ __align__(256) __half g_Kh[(size_t)BB * HH * SS * DD];
__device__ __align__(256) __half g_Kl[(size_t)BB * HH * SS * DD];
__device__ __align__(256) __half g_Vh[(size_t)BB * HH * SS * DD];
__device__ __align__(256) __half g_Vl[(size_t)BB * HH * SS * DD];
__device__ __align__(256) __half g_AOh[(size_t)BB * NN * CC];
__device__ float g_lse[BB * HH * NN];

// ============================================================================
// helpers
// ============================================================================
__device__ __forceinline__ uint32_t smem_u32(const void* p) {
    uint32_t a;
    asm("{ .reg .u64 t; cvta.to.shared.u64 t, %1; cvt.u32.u64 %0, t; }" : "=r"(a) : "l"(p));
    return a;
}
__device__ __forceinline__ void mma_f16(float* c, const uint32_t* a, const uint32_t* b) {
    asm volatile("mma.sync.aligned.m16n8k16.row.col.f32.f16.f16.f32 "
        "{%0,%1,%2,%3}, {%4,%5,%6,%7}, {%8,%9}, {%0,%1,%2,%3};"
        : "+f"(c[0]), "+f"(c[1]), "+f"(c[2]), "+f"(c[3])
        : "r"(a[0]), "r"(a[1]), "r"(a[2]), "r"(a[3]), "r"(b[0]), "r"(b[1]));
}
__device__ __forceinline__ void ldsm_x4(uint32_t* r, uint32_t a) {
    asm volatile("ldmatrix.sync.aligned.m8n8.x4.shared.b16 {%0,%1,%2,%3}, [%4];"
        : "=r"(r[0]), "=r"(r[1]), "=r"(r[2]), "=r"(r[3]) : "r"(a));
}
__device__ __forceinline__ void ldsm_x2(uint32_t* r, uint32_t a) {
    asm volatile("ldmatrix.sync.aligned.m8n8.x2.shared.b16 {%0,%1}, [%2];"
        : "=r"(r[0]), "=r"(r[1]) : "r"(a));
}
__device__ __forceinline__ void ldsm_x2t(uint32_t* r, uint32_t a) {
    asm volatile("ldmatrix.sync.aligned.m8n8.x2.trans.shared.b16 {%0,%1}, [%2];"
        : "=r"(r[0]), "=r"(r[1]) : "r"(a));
}
#define CPA16(dst, src) \
    asm volatile("cp.async.cg.shared.global [%0], [%1], 16;" :: "r"(dst), "l"(src) : "memory")
#define CPA_COMMIT() asm volatile("cp.async.commit_group;" ::: "memory")
#define CPA_WAIT(n)  asm volatile("cp.async.wait_group %0;" :: "n"(n) : "memory")

__device__ __forceinline__ uint32_t packh(float x, float y) {
    __half2 t = __halves2half2(__float2half(x), __float2half(y));
    return *(uint32_t*)&t;
}
__device__ __forceinline__ float hlo(float x) {
    return x - __half2float(__float2half(x));
}

// ============================================================================
// fp32 -> fp16 splits
// ============================================================================
__device__ __forceinline__ void split_hi(const float* __restrict__ x,
                                         __half* __restrict__ hi, int i) {
    float4 v = *(const float4*)(x + (size_t)i * 4);
    *(uint32_t*)(hi + (size_t)i * 4)     = packh(v.x, v.y);
    *(uint32_t*)(hi + (size_t)i * 4 + 2) = packh(v.z, v.w);
}
__device__ __forceinline__ void split_hl(const float* __restrict__ x,
                                         __half* __restrict__ hi,
                                         __half* __restrict__ lo, int i) {
    float4 v = *(const float4*)(x + (size_t)i * 4);
    *(uint32_t*)(hi + (size_t)i * 4)     = packh(v.x, v.y);
    *(uint32_t*)(hi + (size_t)i * 4 + 2) = packh(v.z, v.w);
    *(uint32_t*)(lo + (size_t)i * 4)     = packh(hlo(v.x), hlo(v.y));
    *(uint32_t*)(lo + (size_t)i * 4 + 2) = packh(hlo(v.z), hlo(v.w));
}

__global__ void split_x3(const float* __restrict__ xq, const float* __restrict__ xk,
                         const float* __restrict__ xv, int n4) {
    int i = blockIdx.x * blockDim.x + threadIdx.x;
    if (i >= n4) return;
    if (blockIdx.z == 0)      split_hi(xq, g_xq_h, i);
    else if (blockIdx.z == 1) split_hi(xk, g_xk_h, i);
    else                      split_hi(xv, g_xv_h, i);
}
__global__ void split_w4(const float* __restrict__ wq, const float* __restrict__ wk,
                         const float* __restrict__ wv, const float* __restrict__ wo, int n4) {
    int i = blockIdx.x * blockDim.x + threadIdx.x;
    if (i >= n4) return;
    if (blockIdx.z == 0)      split_hl(wq, g_wq_h, g_wq_l, i);
    else if (blockIdx.z == 1) split_hl(wk, g_wk_h, g_wk_l, i);
    else if (blockIdx.z == 2) split_hl(wv, g_wv_h, g_wv_l, i);
    else                      split_hl(wo, g_wo_h, g_wo_l, i);
}

// ============================================================================
// GEMM mainloop, 256 threads, 128x64 output tile, double-buffered cp.async.
// c[2][4][4] += Xh[128 x CC] . (Wh+Wl)[64 x CC]^T  (2-term fp16).
// ============================================================================
__device__ __forceinline__ void gemm_mainloop256(
    const __half* __restrict__ Xh,
    const __half* __restrict__ Wh, const __half* __restrict__ Wl,
    int m0, int n0, uint32_t s0, int tid, int lane, int wm, int wn,
    float c[2][4][4]) {
    auto issue = [&](int ch, int buf) {
        const uint32_t base = s0 + buf * GBUF;
        #pragma unroll
        for (int t = 0; t < 4; t++) {
            const int id = tid + 256 * t, row = id >> 3, seg = id & 7;
            const uint32_t doff = (uint32_t)(row * LDT + seg * 8) * 2;
            const size_t sx = (size_t)(m0 + row) * CC + ch * 64 + seg * 8;
            CPA16(base + doff, Xh + sx);
        }
        #pragma unroll
        for (int t = 0; t < 2; t++) {
            const int id = tid + 256 * t, row = id >> 3, seg = id & 7;
            const uint32_t doff = (uint32_t)(row * LDT + seg * 8) * 2;
            const size_t sw = (size_t)(n0 + row) * CC + ch * 64 + seg * 8;
            CPA16(base + ATILE + doff, Wh + sw);
            CPA16(base + ATILE + BTILE + doff, Wl + sw);
        }
    };
    issue(0, 0); CPA_COMMIT(); CPA_WAIT(0);
    __syncthreads();
    int buf = 0;
    for (int ch = 0; ch < 12; ch++) {
        if (ch < 11) { issue(ch + 1, buf ^ 1); CPA_COMMIT(); }
        const uint32_t aH = s0 + buf * GBUF;
        const uint32_t bH = aH + ATILE, bL = bH + BTILE;
        #pragma unroll
        for (int ks = 0; ks < 4; ks++) {
            uint32_t ah[2][4], bh[4][2], bl[4][2];
            #pragma unroll
            for (int mi = 0; mi < 2; mi++) {
                uint32_t off = ((wm * 32 + mi * 16 + (lane & 15)) * LDT + ks * 16 + (lane >> 4) * 8) * 2;
                ldsm_x4(ah[mi], aH + off);
            }
            #pragma unroll
            for (int ni = 0; ni < 4; ni++) {
                uint32_t off = ((wn * 32 + ni * 8 + (lane & 7)) * LDT + ks * 16 + ((lane >> 3) & 1) * 8) * 2;
                ldsm_x2(bh[ni], bH + off);
                ldsm_x2(bl[ni], bL + off);
            }
            #pragma unroll
            for (int mi = 0; mi < 2; mi++)
                #pragma unroll
                for (int ni = 0; ni < 4; ni++) {
                    mma_f16(c[mi][ni], ah[mi], bh[ni]);
                    mma_f16(c[mi][ni], ah[mi], bl[ni]);
                }
        }
        CPA_WAIT(0);
        __syncthreads();
        buf ^= 1;
    }
}

// QKV projections merged: grid.z selects tensor; head-major output.
__global__ void __launch_bounds__(256, 2) tc_gemm_qkv() {
    extern __shared__ char sm[];
    const uint32_t s0 = smem_u32(sm);
    const int tid = threadIdx.x, lane = tid & 31, wid = tid >> 5;
    const int wm = wid & 3, wn = wid >> 2;
    const int m0 = blockIdx.y * 128, n0 = blockIdx.x * 64, z = blockIdx.z;
    const __half *Xh, *Wh, *Wl;
    __half *Yh, *Yl;
    if (z == 0)      { Xh = g_xq_h; Wh = g_wq_h; Wl = g_wq_l; Yh = g_Qh; Yl = nullptr; }
    else if (z == 1) { Xh = g_xk_h; Wh = g_wk_h; Wl = g_wk_l; Yh = g_Kh; Yl = g_Kl; }
    else             { Xh = g_xv_h; Wh = g_wv_h; Wl = g_wv_l; Yh = g_Vh; Yl = g_Vl; }

    float c[2][4][4] = {};
    gemm_mainloop256(Xh, Wh, Wl, m0, n0, s0, tid, lane, wm, wn, c);

    const int qr = lane >> 2, qc = (lane & 3) * 2;
    #pragma unroll
    for (int mi = 0; mi < 2; mi++)
        #pragma unroll
        for (int ni = 0; ni < 4; ni++) {
            const int rowg = m0 + wm * 32 + mi * 16 + qr;
            const int b = rowg >> 10, r = rowg & 1023;
            const int col = n0 + wn * 32 + ni * 8 + qc;
            const int h = col >> 6, d = col & 63;
            const size_t o0 = ((size_t)(b * HH + h) * NN + r) * DD + d;
            const size_t o1 = o0 + (size_t)8 * DD;
            float x0 = c[mi][ni][0], x1 = c[mi][ni][1];
            float x2 = c[mi][ni][2], x3 = c[mi][ni][3];
            *(uint32_t*)(Yh + o0) = packh(x0, x1);
            *(uint32_t*)(Yh + o1) = packh(x2, x3);
            if (Yl) {
                *(uint32_t*)(Yl + o0) = packh(hlo(x0), hlo(x1));
                *(uint32_t*)(Yl + o1) = packh(hlo(x2), hlo(x3));
            }
        }
}

// output projection: AOh @ (Wo hi+lo) + bo -> fp32
__global__ void __launch_bounds__(256, 2) tc_gemm_out(const float* __restrict__ bias,
                                                      float* __restrict__ Yf) {
    extern __shared__ char sm[];
    const uint32_t s0 = smem_u32(sm);
    const int tid = threadIdx.x, lane = tid & 31, wid = tid >> 5;
    const int wm = wid & 3, wn = wid >> 2;
    const int m0 = blockIdx.y * 128, n0 = blockIdx.x * 64;

    float c[2][4][4] = {};
    gemm_mainloop256(g_AOh, g_wo_h, g_wo_l, m0, n0, s0, tid, lane, wm, wn, c);

    const int qr = lane >> 2, qc = (lane & 3) * 2;
    #pragma unroll
    for (int mi = 0; mi < 2; mi++)
        #pragma unroll
        for (int ni = 0; ni < 4; ni++) {
            const int row = m0 + wm * 32 + mi * 16 + qr;
            const int col = n0 + wn * 32 + ni * 8 + qc;
            *(float2*)(Yf + (size_t)row * CC + col) =
                make_float2(c[mi][ni][0] + bias[col], c[mi][ni][1] + bias[col + 1]);
            *(float2*)(Yf + (size_t)(row + 8) * CC + col) =
                make_float2(c[mi][ni][2] + bias[col], c[mi][ni][3] + bias[col + 1]);
        }
}

// tile copies (256 threads)
__device__ __forceinline__ void cpa_s64(uint32_t d, const __half* __restrict__ s,
                                        size_t base, int tid) {
    #pragma unroll
    for (int t = 0; t < 2; t++) {
        const int id = tid + 256 * t, row = id >> 3, seg = id & 7;
        CPA16(d + (uint32_t)(row * LDT + seg * 8) * 2, s + base + (size_t)row * 64 + seg * 8);
    }
}
__device__ __forceinline__ void cpa_p64(uint32_t dhi, uint32_t dlo,
                                        const __half* __restrict__ shi,
                                        const __half* __restrict__ slo,
                                        size_t base, int tid) {
    #pragma unroll
    for (int t = 0; t < 2; t++) {
        const int id = tid + 256 * t, row = id >> 3, seg = id & 7;
        const uint32_t doff = (uint32_t)(row * LDT + seg * 8) * 2;
        const size_t s = base + (size_t)row * 64 + seg * 8;
        CPA16(dhi + doff, shi + s);
        CPA16(dlo + doff, slo + s);
    }
}
__device__ __forceinline__ void cpa_p128(uint32_t dhi, uint32_t dlo,
                                         const __half* __restrict__ shi,
                                         const __half* __restrict__ slo,
                                         size_t base, int tid) {
    #pragma unroll
    for (int t = 0; t < 4; t++) {
        const int id = tid + 256 * t, row = id >> 3, seg = id & 7;
        const uint32_t doff = (uint32_t)(row * LDT + seg * 8) * 2;
        const size_t s = base + (size_t)row * 64 + seg * 8;
        CPA16(dhi + doff, shi + s);
        CPA16(dlo + doff, slo + s);
    }
}

// ============================================================================
// Pass 1: lse only (ssum = sum exp(scores)); NO attn_weight stream.
// 256-thread CTA over 64 q-rows, 2 CTAs/SM. fp16 2-term QK.
// smem: Q(9216) + K dbuf(4x18432) + red(1024) = 83968 B.
// ============================================================================
__global__ void __launch_bounds__(256, 2) attn_stats() {
    extern __shared__ char sm[];
    const uint32_t s0 = smem_u32(sm);
    const uint32_t sQH = s0;
    const uint32_t kBase = s0 + QTILEB;
    float* redS = (float*)(sm + QTILEB + 4 * TILEB);

    const int tid = threadIdx.x, lane = tid & 31, wid = tid >> 5;
    const int wm = wid & 1, wn = wid >> 1;
    const int bh = blockIdx.y;
    const int q0 = blockIdx.x * 64;
    const int qr = lane >> 2;

    const size_t qbase = ((size_t)bh * NN + q0) * DD;
    const size_t kbase0 = (size_t)bh * SS * DD;

    cpa_s64(sQH, g_Qh, qbase, tid);
    cpa_p128(kBase, kBase + TILEB, g_Kh, g_Kl, kbase0, tid);
    CPA_COMMIT(); CPA_WAIT(0);
    __syncthreads();

    float ssum[4] = {};

    for (int sc = 0; sc < 8; sc++) {
        const int buf = sc & 1;
        if (sc < 7) {
            const uint32_t kb = kBase + (buf ^ 1) * 2 * TILEB;
            cpa_p128(kb, kb + TILEB, g_Kh, g_Kl, kbase0 + (size_t)(sc + 1) * 128 * DD, tid);
            CPA_COMMIT();
        }
        const uint32_t kH = kBase + buf * 2 * TILEB, kL = kH + TILEB;

        float c[2][4][4] = {};
        #pragma unroll
        for (int ks = 0; ks < 4; ks++) {
            uint32_t ah[2][4], bh2[4][2], bl2[4][2];
            #pragma unroll
            for (int mi = 0; mi < 2; mi++) {
                uint32_t off = ((wm * 32 + mi * 16 + (lane & 15)) * LDT + ks * 16 + (lane >> 4) * 8) * 2;
                ldsm_x4(ah[mi], sQH + off);
            }
            #pragma unroll
            for (int ni = 0; ni < 4; ni++) {
                uint32_t off = ((wn * 32 + ni * 8 + (lane & 7)) * LDT + ks * 16 + ((lane >> 3) & 1) * 8) * 2;
                ldsm_x2(bh2[ni], kH + off);
                ldsm_x2(bl2[ni], kL + off);
            }
            #pragma unroll
            for (int mi = 0; mi < 2; mi++)
                #pragma unroll
                for (int ni = 0; ni < 4; ni++) {
                    mma_f16(c[mi][ni], ah[mi], bh2[ni]);
                    mma_f16(c[mi][ni], ah[mi], bl2[ni]);
                }
        }

        #pragma unroll
        for (int mi = 0; mi < 2; mi++)
            #pragma unroll
            for (int ni = 0; ni < 4; ni++) {
                ssum[mi * 2]     += __expf(c[mi][ni][0] * SCALEF) + __expf(c[mi][ni][1] * SCALEF);
                ssum[mi * 2 + 1] += __expf(c[mi][ni][2] * SCALEF) + __expf(c[mi][ni][3] * SCALEF);
            }
        CPA_WAIT(0);
        __syncthreads();
    }

    #pragma unroll
    for (int sl = 0; sl < 4; sl++) {
        ssum[sl] += __shfl_xor_sync(~0u, ssum[sl], 1);
        ssum[sl] += __shfl_xor_sync(~0u, ssum[sl], 2);
    }
    if ((lane & 3) == 0) {
        #pragma unroll
        for (int sl = 0; sl < 4; sl++) {
            const int row = wm * 32 + (sl >> 1) * 16 + qr + 8 * (sl & 1);
            redS[wn * 64 + row] = ssum[sl];
        }
    }
    __syncthreads();
    if (tid < 64) {
        float st = redS[tid] + redS[64 + tid] + redS[128 + tid] + redS[192 + tid];
        g_lse[bh * NN + q0 + tid] = __logf(st);
    }
}

// ============================================================================
// Pass 2: unnormalized flash-style. P = exp(u) fp16, O' += P@(Vh+Vl),
// usum accumulated inline, final O = O'/usum. lse from stats for logits.
// smem: Q(1) + K dbuf(4) + V(2) + P(1) tiles + red(1024) = 74752 B.
// ============================================================================
__global__ void __launch_bounds__(256, 2) attn_av(const float* __restrict__ AW,
                                                  float* __restrict__ LOGOUT) {
    extern __shared__ char sm[];
    const uint32_t s0 = smem_u32(sm);
    const uint32_t sQH = s0;
    const uint32_t kBase = s0 + QTILEB;                   // 4 x QTILEB
    const uint32_t sVH = s0 + 5 * QTILEB, sVL = s0 + 6 * QTILEB;
    const uint32_t pH = s0 + 7 * QTILEB;
    float* redU = (float*)(sm + 8 * QTILEB);

    const int tid = threadIdx.x, lane = tid & 31, wid = tid >> 5;
    const int wm = wid & 1, wn = wid >> 1;
    const int bh = blockIdx.y;
    const int q0 = blockIdx.x * 64;
    const int qr = lane >> 2, qc = (lane & 3) * 2;

    const size_t qbase = ((size_t)bh * NN + q0) * DD;
    const size_t kvbase = (size_t)bh * SS * DD;

    cpa_s64(sQH, g_Qh, qbase, tid);
    cpa_p64(kBase, kBase + QTILEB, g_Kh, g_Kl, kvbase, tid);
    CPA_COMMIT(); CPA_WAIT(0);
    __syncthreads();

    float lse_r[4];
    #pragma unroll
    for (int sl = 0; sl < 4; sl++) {
        const int row = q0 + wm * 32 + (sl >> 1) * 16 + qr + 8 * (sl & 1);
        lse_r[sl] = g_lse[bh * NN + row];
    }

    float c2[2][2][4] = {};
    float usum[4] = {};

    for (int sc = 0; sc < 16; sc++) {
        const int buf = sc & 1;
        cpa_p64(sVH, sVL, g_Vh, g_Vl, kvbase + (size_t)sc * 64 * DD, tid);
        CPA_COMMIT();
        if (sc < 15) {
            const uint32_t kb = kBase + (buf ^ 1) * 2 * QTILEB;
            cpa_p64(kb, kb + QTILEB, g_Kh, g_Kl, kvbase + (size_t)(sc + 1) * 64 * DD, tid);
            CPA_COMMIT();
        }
        const uint32_t kH = kBase + buf * 2 * QTILEB, kL = kH + QTILEB;

        // ---- QK: 64x64 tile; warp tile 32x16, 2-term
        float c[2][2][4] = {};
        #pragma unroll
        for (int ks = 0; ks < 4; ks++) {
            uint32_t ah[2][4], bh2[2][2], bl2[2][2];
            #pragma unroll
            for (int mi = 0; mi < 2; mi++) {
                uint32_t off = ((wm * 32 + mi * 16 + (lane & 15)) * LDT + ks * 16 + (lane >> 4) * 8) * 2;
                ldsm_x4(ah[mi], sQH + off);
            }
            #pragma unroll
            for (int ni = 0; ni < 2; ni++) {
                uint32_t off = ((wn * 16 + ni * 8 + (lane & 7)) * LDT + ks * 16 + ((lane >> 3) & 1) * 8) * 2;
                ldsm_x2(bh2[ni], kH + off);
                ldsm_x2(bl2[ni], kL + off);
            }
            #pragma unroll
            for (int mi = 0; mi < 2; mi++)
                #pragma unroll
                for (int ni = 0; ni < 2; ni++) {
                    mma_f16(c[mi][ni], ah[mi], bh2[ni]);
                    mma_f16(c[mi][ni], ah[mi], bl2[ni]);
                }
        }

        if (sc < 15) { CPA_WAIT(1); } else { CPA_WAIT(0); }
        __syncthreads();   // V visible; P region free

        // ---- softmax + logits + unnormalized P store
        #pragma unroll
        for (int mi = 0; mi < 2; mi++) {
            const int prow0 = wm * 32 + mi * 16 + qr;
            const size_t rbb = ((size_t)bh * NN + q0 + prow0) * SS + sc * 64;
            #pragma unroll
            for (int ni = 0; ni < 2; ni++) {
                const int col = wn * 16 + ni * 8 + qc;
                const size_t rb = rbb + col;
                float2 aw0 = *(const float2*)(AW + rb);
                float2 aw1 = *(const float2*)(AW + rb + (size_t)8 * SS);
                float u00 = fmaf(c[mi][ni][0], SCALEF, aw0.x);
                float u01 = fmaf(c[mi][ni][1], SCALEF, aw0.y);
                float u10 = fmaf(c[mi][ni][2], SCALEF, aw1.x);
                float u11 = fmaf(c[mi][ni][3], SCALEF, aw1.y);
                const int sl0 = mi * 2, sl1 = mi * 2 + 1;
                *(float2*)(LOGOUT + rb) = make_float2(u00 - lse_r[sl0], u01 - lse_r[sl0]);
                *(float2*)(LOGOUT + rb + (size_t)8 * SS) = make_float2(u10 - lse_r[sl1], u11 - lse_r[sl1]);
                float p00 = __expf(u00), p01 = __expf(u01);
                float p10 = __expf(u10), p11 = __expf(u11);
                usum[sl0] += p00 + p01;
                usum[sl1] += p10 + p11;
                *(uint32_t*)(sm + (pH - s0) + (prow0 * LDT + col) * 2)       = packh(p00, p01);
                *(uint32_t*)(sm + (pH - s0) + ((prow0 + 8) * LDT + col) * 2) = packh(p10, p11);
            }
        }
        __syncthreads();   // P visible

        // ---- PV: O'[64x64] += P[64x64] @ (Vh+Vl)[64x64], warp tile 32x16
        #pragma unroll
        for (int ksp = 0; ksp < 4; ksp++) {
            uint32_t pa[2][4], vh[2][2], vl[2][2];
            #pragma unroll
            for (int mi = 0; mi < 2; mi++) {
                uint32_t off = ((wm * 32 + mi * 16 + (lane & 15)) * LDT + ksp * 16 + (lane >> 4) * 8) * 2;
                ldsm_x4(pa[mi], pH + off);
            }
            #pragma unroll
            for (int nj = 0; nj < 2; nj++) {
                uint32_t off = ((ksp * 16 + (lane & 15)) * LDT + wn * 16 + nj * 8) * 2;
                ldsm_x2t(vh[nj], sVH + off);
                ldsm_x2t(vl[nj], sVL + off);
            }
            #pragma unroll
            for (int mi = 0; mi < 2; mi++)
                #pragma unroll
                for (int nj = 0; nj < 2; nj++) {
                    mma_f16(c2[mi][nj], pa[mi], vh[nj]);
                    mma_f16(c2[mi][nj], pa[mi], vl[nj]);
                }
        }
        CPA_WAIT(0);
        __syncthreads();   // K swap + V/P reuse safe
    }

    // ---- reduce usum across lanes and wn groups -> 1/usum per row
    #pragma unroll
    for (int sl = 0; sl < 4; sl++) {
        usum[sl] += __shfl_xor_sync(~0u, usum[sl], 1);
        usum[sl] += __shfl_xor_sync(~0u, usum[sl], 2);
    }
    if ((lane & 3) == 0) {
        #pragma unroll
        for (int sl = 0; sl < 4; sl++) {
            const int row = wm * 32 + (sl >> 1) * 16 + qr + 8 * (sl & 1);
            redU[wn * 64 + row] = usum[sl];
        }
    }
    __syncthreads();
    if (tid < 64) {
        float t = redU[tid] + redU[64 + tid] + redU[128 + tid] + redU[192 + tid];
        redU[tid] = 1.0f / t;
    }
    __syncthreads();

    const int b = bh / HH, h = bh % HH;
    #pragma unroll
    for (int mi = 0; mi < 2; mi++) {
        const float is0 = redU[wm * 32 + mi * 16 + qr];
        const float is1 = redU[wm * 32 + mi * 16 + qr + 8];
        #pragma unroll
        for (int nj = 0; nj < 2; nj++) {
            const int row = q0 + wm * 32 + mi * 16 + qr;
            const int col = h * DD + wn * 16 + nj * 8 + qc;
            const size_t o0 = (size_t)(b * NN + row) * CC + col;
            const size_t o1 = (size_t)(b * NN + row + 8) * CC + col;
            *(uint32_t*)(g_AOh + o0) = packh(c2[mi][nj][0] * is0, c2[mi][nj][1] * is0);
            *(uint32_t*)(g_AOh + o1) = packh(c2[mi][nj][2] * is1, c2[mi][nj][3] * is1);
        }
    }
}

// ============================================================================
extern "C" void kernel_launch(void* const* d_in, const int* in_sizes, int n_in,
                              void* d_out, int out_size) {
    const float* query = (const float*)d_in[0];
    const float* key_  = (const float*)d_in[1];
    const float* value = (const float*)d_in[2];
    const float* aw    = (const float*)d_in[3];
    const float* Wq    = (const float*)d_in[4];
    const float* Wk    = (const float*)d_in[5];
    const float* Wv    = (const float*)d_in[6];
    const float* Wo    = (const float*)d_in[7];
    const float* bo    = (const float*)d_in[8];

    float* out    = (float*)d_out;                       // [B,N,C]
    float* logout = out + (size_t)BB * NN * CC;          // [B,H,N,S]

    const int smem_gemm  = 2 * GBUF;                      // 73728
    const int smem_stats = QTILEB + 4 * TILEB + 1024;     // 83968
    const int smem_av    = 8 * QTILEB + 1024;             // 74752
    cudaFuncSetAttribute(tc_gemm_qkv, cudaFuncAttributeMaxDynamicSharedMemorySize, smem_gemm);
    cudaFuncSetAttribute(tc_gemm_out, cudaFuncAttributeMaxDynamicSharedMemorySize, smem_gemm);
    cudaFuncSetAttribute(attn_stats,  cudaFuncAttributeMaxDynamicSharedMemorySize, smem_stats);
    cudaFuncSetAttribute(attn_av,     cudaFuncAttributeMaxDynamicSharedMemorySize, smem_av);

    const int nX4 = (BB * NN * CC) / 4;
    const int nW4 = (CC * CC) / 4;
    dim3 gsx((nX4 + 255) / 256, 1, 3);
    dim3 gsw((nW4 + 255) / 256, 1, 4);
    dim3 gqkv(CC / 64, (BB * NN) / 128, 3);    // 12 x 64 x 3
    dim3 gp(CC / 64, (BB * NN) / 128);         // 12 x 64
    dim3 gst(NN / 64, BB * HH);                // 16 x 96
    dim3 gav(NN / 64, BB * HH);                // 16 x 96

    split_x3<<<gsx, 256>>>(query, key_, value, nX4);
    split_w4<<<gsw, 256>>>(Wq, Wk, Wv, Wo, nW4);
    tc_gemm_qkv<<<gqkv, 256, smem_gemm>>>();
    attn_stats<<<gst, 256, smem_stats>>>();
    attn_av<<<gav, 256, smem_av>>>(aw, logout);
    tc_gemm_out<<<gp, 256, smem_gemm>>>(bo, out);
}

// round 16
// speedup vs baseline: 1.8928x; 1.2605x over previous
#include <cuda_runtime.h>
#include <cuda_fp16.h>
#include <math.h>
#include <stdint.h>

#define BB 8
#define NN 1024
#define SS 1024
#define CC 768
#define HH 12
#define DD 64
#define SCALEF 0.125f

#define LDT 72        // fp16 elems per 64-wide tile row (144B, conflict-free)
#define TILEB (128 * LDT * 2)   // 18432 B per 128x64 fp16 tile
#define QTILEB (64 * LDT * 2)   // 9216 B per 64x64 fp16 tile
#define ATILE 18432
#define BTILE 9216
#define GBUF (ATILE + BTILE)    // 27648 per gemm buffer (A + B, both single fp16)

// -------- scratch (device globals; no allocation allowed) --------
__device__ __align__(256) __half g_xq_h[(size_t)BB * NN * CC];
__device__ __align__(256) __half g_xk_h[(size_t)BB * SS * CC];
__device__ __align__(256) __half g_xv_h[(size_t)BB * SS * CC];
__device__ __align__(256) __half g_wq_h[(size_t)CC * CC];
__device__ __align__(256) __half g_wk_h[(size_t)CC * CC];
__device__ __align__(256) __half g_wv_h[(size_t)CC * CC];
__device__ __align__(256) __half g_wo_h[(size_t)CC * CC];
__device__ __align__(256) __half g_Qh[(size_t)BB * HH * NN * DD];
__device__ __align__(256) __half g_Kh[(size_t)BB * HH * SS * DD];
__device__ __align__(256) __half g_Vh[(size_t)BB * HH * SS * DD];
__device__ __align__(256) __half g_AOh[(size_t)BB * NN * CC];
__device__ float g_lse[BB * HH * NN];

// ============================================================================
// helpers
// ============================================================================
__device__ __forceinline__ uint32_t smem_u32(const void* p) {
    uint32_t a;
    asm("{ .reg .u64 t; cvta.to.shared.u64 t, %1; cvt.u32.u64 %0, t; }" : "=r"(a) : "l"(p));
    return a;
}
__device__ __forceinline__ void mma_f16(float* c, const uint32_t* a, const uint32_t* b) {
    asm volatile("mma.sync.aligned.m16n8k16.row.col.f32.f16.f16.f32 "
        "{%0,%1,%2,%3}, {%4,%5,%6,%7}, {%8,%9}, {%0,%1,%2,%3};"
        : "+f"(c[0]), "+f"(c[1]), "+f"(c[2]), "+f"(c[3])
        : "r"(a[0]), "r"(a[1]), "r"(a[2]), "r"(a[3]), "r"(b[0]), "r"(b[1]));
}
__device__ __forceinline__ void ldsm_x4(uint32_t* r, uint32_t a) {
    asm volatile("ldmatrix.sync.aligned.m8n8.x4.shared.b16 {%0,%1,%2,%3}, [%4];"
        : "=r"(r[0]), "=r"(r[1]), "=r"(r[2]), "=r"(r[3]) : "r"(a));
}
__device__ __forceinline__ void ldsm_x2(uint32_t* r, uint32_t a) {
    asm volatile("ldmatrix.sync.aligned.m8n8.x2.shared.b16 {%0,%1}, [%2];"
        : "=r"(r[0]), "=r"(r[1]) : "r"(a));
}
__device__ __forceinline__ void ldsm_x2t(uint32_t* r, uint32_t a) {
    asm volatile("ldmatrix.sync.aligned.m8n8.x2.trans.shared.b16 {%0,%1}, [%2];"
        : "=r"(r[0]), "=r"(r[1]) : "r"(a));
}
#define CPA16(dst, src) \
    asm volatile("cp.async.cg.shared.global [%0], [%1], 16;" :: "r"(dst), "l"(src) : "memory")
#define CPA_COMMIT() asm volatile("cp.async.commit_group;" ::: "memory")
#define CPA_WAIT(n)  asm volatile("cp.async.wait_group %0;" :: "n"(n) : "memory")

__device__ __forceinline__ uint32_t packh(float x, float y) {
    __half2 t = __halves2half2(__float2half(x), __float2half(y));
    return *(uint32_t*)&t;
}

// ============================================================================
// fp32 -> fp16 convert; z selects tensor
// ============================================================================
__device__ __forceinline__ void cvt_hi(const float* __restrict__ x,
                                       __half* __restrict__ hi, int i) {
    float4 v = *(const float4*)(x + (size_t)i * 4);
    *(uint32_t*)(hi + (size_t)i * 4)     = packh(v.x, v.y);
    *(uint32_t*)(hi + (size_t)i * 4 + 2) = packh(v.z, v.w);
}

__global__ void split_x3(const float* __restrict__ xq, const float* __restrict__ xk,
                         const float* __restrict__ xv, int n4) {
    int i = blockIdx.x * blockDim.x + threadIdx.x;
    if (i >= n4) return;
    if (blockIdx.z == 0)      cvt_hi(xq, g_xq_h, i);
    else if (blockIdx.z == 1) cvt_hi(xk, g_xk_h, i);
    else                      cvt_hi(xv, g_xv_h, i);
}
__global__ void split_w4(const float* __restrict__ wq, const float* __restrict__ wk,
                         const float* __restrict__ wv, const float* __restrict__ wo, int n4) {
    int i = blockIdx.x * blockDim.x + threadIdx.x;
    if (i >= n4) return;
    if (blockIdx.z == 0)      cvt_hi(wq, g_wq_h, i);
    else if (blockIdx.z == 1) cvt_hi(wk, g_wk_h, i);
    else if (blockIdx.z == 2) cvt_hi(wv, g_wv_h, i);
    else                      cvt_hi(wo, g_wo_h, i);
}

// ============================================================================
// GEMM mainloop, 256 threads, 128x64 output tile, plain fp16, dbuf cp.async.
// c[2][4][4] += X[128 x CC] . W[64 x CC]^T
// ============================================================================
__device__ __forceinline__ void gemm_mainloop256(
    const __half* __restrict__ Xh, const __half* __restrict__ Wh,
    int m0, int n0, uint32_t s0, int tid, int lane, int wm, int wn,
    float c[2][4][4]) {
    auto issue = [&](int ch, int buf) {
        const uint32_t base = s0 + buf * GBUF;
        #pragma unroll
        for (int t = 0; t < 4; t++) {
            const int id = tid + 256 * t, row = id >> 3, seg = id & 7;
            const uint32_t doff = (uint32_t)(row * LDT + seg * 8) * 2;
            CPA16(base + doff, Xh + (size_t)(m0 + row) * CC + ch * 64 + seg * 8);
        }
        #pragma unroll
        for (int t = 0; t < 2; t++) {
            const int id = tid + 256 * t, row = id >> 3, seg = id & 7;
            const uint32_t doff = (uint32_t)(row * LDT + seg * 8) * 2;
            CPA16(base + ATILE + doff, Wh + (size_t)(n0 + row) * CC + ch * 64 + seg * 8);
        }
    };
    issue(0, 0); CPA_COMMIT(); CPA_WAIT(0);
    __syncthreads();
    int buf = 0;
    for (int ch = 0; ch < 12; ch++) {
        if (ch < 11) { issue(ch + 1, buf ^ 1); CPA_COMMIT(); }
        const uint32_t aH = s0 + buf * GBUF;
        const uint32_t bH = aH + ATILE;
        #pragma unroll
        for (int ks = 0; ks < 4; ks++) {
            uint32_t ah[2][4], bh[4][2];
            #pragma unroll
            for (int mi = 0; mi < 2; mi++) {
                uint32_t off = ((wm * 32 + mi * 16 + (lane & 15)) * LDT + ks * 16 + (lane >> 4) * 8) * 2;
                ldsm_x4(ah[mi], aH + off);
            }
            #pragma unroll
            for (int ni = 0; ni < 4; ni++) {
                uint32_t off = ((wn * 32 + ni * 8 + (lane & 7)) * LDT + ks * 16 + ((lane >> 3) & 1) * 8) * 2;
                ldsm_x2(bh[ni], bH + off);
            }
            #pragma unroll
            for (int mi = 0; mi < 2; mi++)
                #pragma unroll
                for (int ni = 0; ni < 4; ni++)
                    mma_f16(c[mi][ni], ah[mi], bh[ni]);
        }
        CPA_WAIT(0);
        __syncthreads();
        buf ^= 1;
    }
}

// QKV projections merged: grid.z selects tensor; head-major fp16 output
__global__ void __launch_bounds__(256, 2) tc_gemm_qkv() {
    extern __shared__ char sm[];
    const uint32_t s0 = smem_u32(sm);
    const int tid = threadIdx.x, lane = tid & 31, wid = tid >> 5;
    const int wm = wid & 3, wn = wid >> 2;
    const int m0 = blockIdx.y * 128, n0 = blockIdx.x * 64, z = blockIdx.z;
    const __half *Xh, *Wh;
    __half *Yh;
    if (z == 0)      { Xh = g_xq_h; Wh = g_wq_h; Yh = g_Qh; }
    else if (z == 1) { Xh = g_xk_h; Wh = g_wk_h; Yh = g_Kh; }
    else             { Xh = g_xv_h; Wh = g_wv_h; Yh = g_Vh; }

    float c[2][4][4] = {};
    gemm_mainloop256(Xh, Wh, m0, n0, s0, tid, lane, wm, wn, c);

    const int qr = lane >> 2, qc = (lane & 3) * 2;
    #pragma unroll
    for (int mi = 0; mi < 2; mi++)
        #pragma unroll
        for (int ni = 0; ni < 4; ni++) {
            const int rowg = m0 + wm * 32 + mi * 16 + qr;
            const int b = rowg >> 10, r = rowg & 1023;
            const int col = n0 + wn * 32 + ni * 8 + qc;
            const int h = col >> 6, d = col & 63;
            const size_t o0 = ((size_t)(b * HH + h) * NN + r) * DD + d;
            const size_t o1 = o0 + (size_t)8 * DD;
            *(uint32_t*)(Yh + o0) = packh(c[mi][ni][0], c[mi][ni][1]);
            *(uint32_t*)(Yh + o1) = packh(c[mi][ni][2], c[mi][ni][3]);
        }
}

// output projection: AOh @ Wo + bo -> fp32
__global__ void __launch_bounds__(256, 2) tc_gemm_out(const float* __restrict__ bias,
                                                      float* __restrict__ Yf) {
    extern __shared__ char sm[];
    const uint32_t s0 = smem_u32(sm);
    const int tid = threadIdx.x, lane = tid & 31, wid = tid >> 5;
    const int wm = wid & 3, wn = wid >> 2;
    const int m0 = blockIdx.y * 128, n0 = blockIdx.x * 64;

    float c[2][4][4] = {};
    gemm_mainloop256(g_AOh, g_wo_h, m0, n0, s0, tid, lane, wm, wn, c);

    const int qr = lane >> 2, qc = (lane & 3) * 2;
    #pragma unroll
    for (int mi = 0; mi < 2; mi++)
        #pragma unroll
        for (int ni = 0; ni < 4; ni++) {
            const int row = m0 + wm * 32 + mi * 16 + qr;
            const int col = n0 + wn * 32 + ni * 8 + qc;
            *(float2*)(Yf + (size_t)row * CC + col) =
                make_float2(c[mi][ni][0] + bias[col], c[mi][ni][1] + bias[col + 1]);
            *(float2*)(Yf + (size_t)(row + 8) * CC + col) =
                make_float2(c[mi][ni][2] + bias[col], c[mi][ni][3] + bias[col + 1]);
        }
}

// tile copies (256 threads), single fp16 tiles
__device__ __forceinline__ void cpa_s64(uint32_t d, const __half* __restrict__ s,
                                        size_t base, int tid) {
    #pragma unroll
    for (int t = 0; t < 2; t++) {
        const int id = tid + 256 * t, row = id >> 3, seg = id & 7;
        CPA16(d + (uint32_t)(row * LDT + seg * 8) * 2, s + base + (size_t)row * 64 + seg * 8);
    }
}
__device__ __forceinline__ void cpa_s128(uint32_t d, const __half* __restrict__ s,
                                         size_t base, int tid) {
    #pragma unroll
    for (int t = 0; t < 4; t++) {
        const int id = tid + 256 * t, row = id >> 3, seg = id & 7;
        CPA16(d + (uint32_t)(row * LDT + seg * 8) * 2, s + base + (size_t)row * 64 + seg * 8);
    }
}

// ============================================================================
// Pass 1: lse only. Plain fp16 QK. 256 threads, 64 q-rows, 2 CTAs/SM.
// smem: Q(9216) + K dbuf(2x18432) + red(1024) = 47104 B.
// ============================================================================
__global__ void __launch_bounds__(256, 2) attn_stats() {
    extern __shared__ char sm[];
    const uint32_t s0 = smem_u32(sm);
    const uint32_t sQH = s0;
    const uint32_t kBase = s0 + QTILEB;
    float* redS = (float*)(sm + QTILEB + 2 * TILEB);

    const int tid = threadIdx.x, lane = tid & 31, wid = tid >> 5;
    const int wm = wid & 1, wn = wid >> 1;
    const int bh = blockIdx.y;
    const int q0 = blockIdx.x * 64;
    const int qr = lane >> 2;

    const size_t qbase = ((size_t)bh * NN + q0) * DD;
    const size_t kbase0 = (size_t)bh * SS * DD;

    cpa_s64(sQH, g_Qh, qbase, tid);
    cpa_s128(kBase, g_Kh, kbase0, tid);
    CPA_COMMIT(); CPA_WAIT(0);
    __syncthreads();

    float ssum[4] = {};

    for (int sc = 0; sc < 8; sc++) {
        const int buf = sc & 1;
        if (sc < 7) {
            cpa_s128(kBase + (buf ^ 1) * TILEB, g_Kh, kbase0 + (size_t)(sc + 1) * 128 * DD, tid);
            CPA_COMMIT();
        }
        const uint32_t kH = kBase + buf * TILEB;

        float c[2][4][4] = {};
        #pragma unroll
        for (int ks = 0; ks < 4; ks++) {
            uint32_t ah[2][4], bh2[4][2];
            #pragma unroll
            for (int mi = 0; mi < 2; mi++) {
                uint32_t off = ((wm * 32 + mi * 16 + (lane & 15)) * LDT + ks * 16 + (lane >> 4) * 8) * 2;
                ldsm_x4(ah[mi], sQH + off);
            }
            #pragma unroll
            for (int ni = 0; ni < 4; ni++) {
                uint32_t off = ((wn * 32 + ni * 8 + (lane & 7)) * LDT + ks * 16 + ((lane >> 3) & 1) * 8) * 2;
                ldsm_x2(bh2[ni], kH + off);
            }
            #pragma unroll
            for (int mi = 0; mi < 2; mi++)
                #pragma unroll
                for (int ni = 0; ni < 4; ni++)
                    mma_f16(c[mi][ni], ah[mi], bh2[ni]);
        }

        #pragma unroll
        for (int mi = 0; mi < 2; mi++)
            #pragma unroll
            for (int ni = 0; ni < 4; ni++) {
                ssum[mi * 2]     += __expf(c[mi][ni][0] * SCALEF) + __expf(c[mi][ni][1] * SCALEF);
                ssum[mi * 2 + 1] += __expf(c[mi][ni][2] * SCALEF) + __expf(c[mi][ni][3] * SCALEF);
            }
        CPA_WAIT(0);
        __syncthreads();
    }

    #pragma unroll
    for (int sl = 0; sl < 4; sl++) {
        ssum[sl] += __shfl_xor_sync(~0u, ssum[sl], 1);
        ssum[sl] += __shfl_xor_sync(~0u, ssum[sl], 2);
    }
    if ((lane & 3) == 0) {
        #pragma unroll
        for (int sl = 0; sl < 4; sl++) {
            const int row = wm * 32 + (sl >> 1) * 16 + qr + 8 * (sl & 1);
            redS[wn * 64 + row] = ssum[sl];
        }
    }
    __syncthreads();
    if (tid < 64) {
        float st = redS[tid] + redS[64 + tid] + redS[128 + tid] + redS[192 + tid];
        g_lse[bh * NN + q0 + tid] = __logf(st);
    }
}

// ============================================================================
// Pass 2: unnormalized flash-style, plain fp16. P = exp(u), O' += P@V,
// usum inline, final O = O'/usum. 256 threads, 64 q-rows, 2 CTAs/SM.
// smem: Q(1) + K dbuf(2) + V(1) + P(1) = 5*9216 + red(1024) = 47104 B.
// ============================================================================
__global__ void __launch_bounds__(256, 2) attn_av(const float* __restrict__ AW,
                                                  float* __restrict__ LOGOUT) {
    extern __shared__ char sm[];
    const uint32_t s0 = smem_u32(sm);
    const uint32_t sQH = s0;
    const uint32_t kBase = s0 + QTILEB;                   // 2 x QTILEB
    const uint32_t sVH = s0 + 3 * QTILEB;
    const uint32_t pH = s0 + 4 * QTILEB;
    float* redU = (float*)(sm + 5 * QTILEB);

    const int tid = threadIdx.x, lane = tid & 31, wid = tid >> 5;
    const int wm = wid & 1, wn = wid >> 1;
    const int bh = blockIdx.y;
    const int q0 = blockIdx.x * 64;
    const int qr = lane >> 2, qc = (lane & 3) * 2;

    const size_t qbase = ((size_t)bh * NN + q0) * DD;
    const size_t kvbase = (size_t)bh * SS * DD;

    cpa_s64(sQH, g_Qh, qbase, tid);
    cpa_s64(kBase, g_Kh, kvbase, tid);
    CPA_COMMIT(); CPA_WAIT(0);
    __syncthreads();

    float lse_r[4];
    #pragma unroll
    for (int sl = 0; sl < 4; sl++) {
        const int row = q0 + wm * 32 + (sl >> 1) * 16 + qr + 8 * (sl & 1);
        lse_r[sl] = g_lse[bh * NN + row];
    }

    float c2[2][2][4] = {};
    float usum[4] = {};

    for (int sc = 0; sc < 16; sc++) {
        const int buf = sc & 1;
        cpa_s64(sVH, g_Vh, kvbase + (size_t)sc * 64 * DD, tid);
        CPA_COMMIT();
        if (sc < 15) {
            cpa_s64(kBase + (buf ^ 1) * QTILEB, g_Kh, kvbase + (size_t)(sc + 1) * 64 * DD, tid);
            CPA_COMMIT();
        }
        const uint32_t kH = kBase + buf * QTILEB;

        // ---- QK: 64x64 tile; warp tile 32x16
        float c[2][2][4] = {};
        #pragma unroll
        for (int ks = 0; ks < 4; ks++) {
            uint32_t ah[2][4], bh2[2][2];
            #pragma unroll
            for (int mi = 0; mi < 2; mi++) {
                uint32_t off = ((wm * 32 + mi * 16 + (lane & 15)) * LDT + ks * 16 + (lane >> 4) * 8) * 2;
                ldsm_x4(ah[mi], sQH + off);
            }
            #pragma unroll
            for (int ni = 0; ni < 2; ni++) {
                uint32_t off = ((wn * 16 + ni * 8 + (lane & 7)) * LDT + ks * 16 + ((lane >> 3) & 1) * 8) * 2;
                ldsm_x2(bh2[ni], kH + off);
            }
            #pragma unroll
            for (int mi = 0; mi < 2; mi++)
                #pragma unroll
                for (int ni = 0; ni < 2; ni++)
                    mma_f16(c[mi][ni], ah[mi], bh2[ni]);
        }

        if (sc < 15) { CPA_WAIT(1); } else { CPA_WAIT(0); }
        __syncthreads();   // V visible; P region free

        // ---- softmax + logits + unnormalized P store
        #pragma unroll
        for (int mi = 0; mi < 2; mi++) {
            const int prow0 = wm * 32 + mi * 16 + qr;
            const size_t rbb = ((size_t)bh * NN + q0 + prow0) * SS + sc * 64;
            #pragma unroll
            for (int ni = 0; ni < 2; ni++) {
                const int col = wn * 16 + ni * 8 + qc;
                const size_t rb = rbb + col;
                float2 aw0 = *(const float2*)(AW + rb);
                float2 aw1 = *(const float2*)(AW + rb + (size_t)8 * SS);
                float u00 = fmaf(c[mi][ni][0], SCALEF, aw0.x);
                float u01 = fmaf(c[mi][ni][1], SCALEF, aw0.y);
                float u10 = fmaf(c[mi][ni][2], SCALEF, aw1.x);
                float u11 = fmaf(c[mi][ni][3], SCALEF, aw1.y);
                const int sl0 = mi * 2, sl1 = mi * 2 + 1;
                *(float2*)(LOGOUT + rb) = make_float2(u00 - lse_r[sl0], u01 - lse_r[sl0]);
                *(float2*)(LOGOUT + rb + (size_t)8 * SS) = make_float2(u10 - lse_r[sl1], u11 - lse_r[sl1]);
                float p00 = __expf(u00), p01 = __expf(u01);
                float p10 = __expf(u10), p11 = __expf(u11);
                usum[sl0] += p00 + p01;
                usum[sl1] += p10 + p11;
                *(uint32_t*)(sm + (pH - s0) + (prow0 * LDT + col) * 2)       = packh(p00, p01);
                *(uint32_t*)(sm + (pH - s0) + ((prow0 + 8) * LDT + col) * 2) = packh(p10, p11);
            }
        }
        __syncthreads();   // P visible

        // ---- PV: O'[64x64] += P[64x64] @ V[64x64], warp tile 32x16
        #pragma unroll
        for (int ksp = 0; ksp < 4; ksp++) {
            uint32_t pa[2][4], vh[2][2];
            #pragma unroll
            for (int mi = 0; mi < 2; mi++) {
                uint32_t off = ((wm * 32 + mi * 16 + (lane & 15)) * LDT + ksp * 16 + (lane >> 4) * 8) * 2;
                ldsm_x4(pa[mi], pH + off);
            }
            #pragma unroll
            for (int nj = 0; nj < 2; nj++) {
                uint32_t off = ((ksp * 16 + (lane & 15)) * LDT + wn * 16 + nj * 8) * 2;
                ldsm_x2t(vh[nj], sVH + off);
            }
            #pragma unroll
            for (int mi = 0; mi < 2; mi++)
                #pragma unroll
                for (int nj = 0; nj < 2; nj++)
                    mma_f16(c2[mi][nj], pa[mi], vh[nj]);
        }
        CPA_WAIT(0);
        __syncthreads();   // K swap + V/P reuse safe
    }

    // ---- reduce usum across lanes and wn groups -> 1/usum per row
    #pragma unroll
    for (int sl = 0; sl < 4; sl++) {
        usum[sl] += __shfl_xor_sync(~0u, usum[sl], 1);
        usum[sl] += __shfl_xor_sync(~0u, usum[sl], 2);
    }
    if ((lane & 3) == 0) {
        #pragma unroll
        for (int sl = 0; sl < 4; sl++) {
            const int row = wm * 32 + (sl >> 1) * 16 + qr + 8 * (sl & 1);
            redU[wn * 64 + row] = usum[sl];
        }
    }
    __syncthreads();
    if (tid < 64) {
        float t = redU[tid] + redU[64 + tid] + redU[128 + tid] + redU[192 + tid];
        redU[tid] = 1.0f / t;
    }
    __syncthreads();

    const int b = bh / HH, h = bh % HH;
    #pragma unroll
    for (int mi = 0; mi < 2; mi++) {
        const float is0 = redU[wm * 32 + mi * 16 + qr];
        const float is1 = redU[wm * 32 + mi * 16 + qr + 8];
        #pragma unroll
        for (int nj = 0; nj < 2; nj++) {
            const int row = q0 + wm * 32 + mi * 16 + qr;
            const int col = h * DD + wn * 16 + nj * 8 + qc;
            const size_t o0 = (size_t)(b * NN + row) * CC + col;
            const size_t o1 = (size_t)(b * NN + row + 8) * CC + col;
            *(uint32_t*)(g_AOh + o0) = packh(c2[mi][nj][0] * is0, c2[mi][nj][1] * is0);
            *(uint32_t*)(g_AOh + o1) = packh(c2[mi][nj][2] * is1, c2[mi][nj][3] * is1);
        }
    }
}

// ============================================================================
extern "C" void kernel_launch(void* const* d_in, const int* in_sizes, int n_in,
                              void* d_out, int out_size) {
    const float* query = (const float*)d_in[0];
    const float* key_  = (const float*)d_in[1];
    const float* value = (const float*)d_in[2];
    const float* aw    = (const float*)d_in[3];
    const float* Wq    = (const float*)d_in[4];
    const float* Wk    = (const float*)d_in[5];
    const float* Wv    = (const float*)d_in[6];
    const float* Wo    = (const float*)d_in[7];
    const float* bo    = (const float*)d_in[8];

    float* out    = (float*)d_out;                       // [B,N,C]
    float* logout = out + (size_t)BB * NN * CC;          // [B,H,N,S]

    const int smem_gemm  = 2 * GBUF;                      // 55296
    const int smem_stats = QTILEB + 2 * TILEB + 1024;     // 47104
    const int smem_av    = 5 * QTILEB + 1024;             // 47104
    cudaFuncSetAttribute(tc_gemm_qkv, cudaFuncAttributeMaxDynamicSharedMemorySize, smem_gemm);
    cudaFuncSetAttribute(tc_gemm_out, cudaFuncAttributeMaxDynamicSharedMemorySize, smem_gemm);
    cudaFuncSetAttribute(attn_stats,  cudaFuncAttributeMaxDynamicSharedMemorySize, smem_stats);
    cudaFuncSetAttribute(attn_av,     cudaFuncAttributeMaxDynamicSharedMemorySize, smem_av);

    const int nX4 = (BB * NN * CC) / 4;
    const int nW4 = (CC * CC) / 4;
    dim3 gsx((nX4 + 255) / 256, 1, 3);
    dim3 gsw((nW4 + 255) / 256, 1, 4);
    dim3 gqkv(CC / 64, (BB * NN) / 128, 3);    // 12 x 64 x 3
    dim3 gp(CC / 64, (BB * NN) / 128);         // 12 x 64
    dim3 gst(NN / 64, BB * HH);                // 16 x 96
    dim3 gav(NN / 64, BB * HH);                // 16 x 96

    split_x3<<<gsx, 256>>>(query, key_, value, nX4);
    split_w4<<<gsw, 256>>>(Wq, Wk, Wv, Wo, nW4);
    tc_gemm_qkv<<<gqkv, 256, smem_gemm>>>();
    attn_stats<<<gst, 256, smem_stats>>>();
    attn_av<<<gav, 256, smem_av>>>(aw, logout);
    tc_gemm_out<<<gp, 256, smem_gemm>>>(bo, out);
}